// round 11
// baseline (speedup 1.0000x reference)
#include <cuda_runtime.h>
#include <cuda_bf16.h>
#include <cstdint>
#include <cstddef>

#define NI 64
#define NH 32
#define HW 16384

__device__ float d_c[128];
__device__ float d_s[128];

__device__ float s_xan [NI*HW];
__device__ float s_F1  [NI*128*33*2];
__device__ float s_F2  [NI*64*33*2];
__device__ float s_qh  [(size_t)NI*NH*4224];
__device__ float s_kh  [(size_t)NI*NH*4224];
__device__ float s_scp [11*64*1024];
__device__ float s_attn[64*1024];
__device__ float s_vhat [(size_t)NI*NH*4096];
__device__ float s_svhat[(size_t)NI*NH*1024];
__device__ float s_sghat[(size_t)NI*NH*1024];
__device__ float s_PFp [(size_t)8*NI*4096];
__device__ float s_y2  [NI*HW];
__device__ float s_fno [NI*HW];
__device__ float s_att [NI*HW];
__device__ float s_an  [NI*HW];
__device__ float s_m   [NI*HW];
__device__ float s_MF1 [NI*128*32*2];
__device__ float s_MF2 [NI*64*32*2];

__device__ __forceinline__ void load_tables(float* cs, float* ss) {
    for (int t = threadIdx.x; t < 128; t += blockDim.x) { cs[t] = d_c[t]; ss[t] = d_s[t]; }
}

__global__ void k_init() {
    int k = threadIdx.x;
    d_c[k] = cospif(k / 64.0f);
    d_s[k] = sinpif(k / 64.0f);
}

// block stats via warp shuffles; 512 threads
__device__ __forceinline__ void block_stats(float sum, float sq, float* shm,
                                            float& mean, float& istd) {
    #pragma unroll
    for (int o = 16; o; o >>= 1) {
        sum += __shfl_xor_sync(0xffffffffu, sum, o);
        sq  += __shfl_xor_sync(0xffffffffu, sq, o);
    }
    int wid = threadIdx.x >> 5;
    if ((threadIdx.x & 31) == 0) { shm[wid] = sum; shm[16 + wid] = sq; }
    __syncthreads();
    if (threadIdx.x < 32) {
        float a = (threadIdx.x < 16) ? shm[threadIdx.x] : 0.f;
        float b = (threadIdx.x < 16) ? shm[16 + threadIdx.x] : 0.f;
        #pragma unroll
        for (int o = 8; o; o >>= 1) {
            a += __shfl_xor_sync(0xffffffffu, a, o);
            b += __shfl_xor_sync(0xffffffffu, b, o);
        }
        if (threadIdx.x == 0) {
            float m = a * (1.f / HW);
            float var = b * (1.f / HW) - m * m;
            shm[32] = m; shm[33] = rsqrtf(var + 1e-5f);
        }
    }
    __syncthreads();
    mean = shm[32]; istd = shm[33];
}

// -------- instance norm (512 thr, float4); optional pre-add & post-add
__global__ void k_inorm(const float* __restrict__ src, const float* __restrict__ add,
                        float* __restrict__ dst, const float* __restrict__ gA,
                        const float* __restrict__ bA, int gi, const float* __restrict__ post) {
    int img = blockIdx.x, tid = threadIdx.x;
    const float4* s4 = (const float4*)(src + (size_t)img * HW);
    const float4* a4 = add ? (const float4*)(add + (size_t)img * HW) : nullptr;
    const float4* p4 = post ? (const float4*)(post + (size_t)img * HW) : nullptr;
    float4* d4 = (float4*)(dst + (size_t)img * HW);
    float sum = 0.f, sq = 0.f;
    for (int p = tid; p < 4096; p += 512) {
        float4 v = s4[p];
        if (a4) { float4 a = a4[p]; v.x += a.x; v.y += a.y; v.z += a.z; v.w += a.w; }
        sum += v.x + v.y + v.z + v.w;
        sq += v.x * v.x + v.y * v.y + v.z * v.z + v.w * v.w;
    }
    __shared__ float shm[34];
    float m, is;
    block_stats(sum, sq, shm, m, is);
    float g = gA[gi], bb = bA[gi];
    for (int p = tid; p < 4096; p += 512) {
        float4 v = s4[p];
        if (a4) { float4 a = a4[p]; v.x += a.x; v.y += a.y; v.z += a.z; v.w += a.w; }
        float4 r;
        r.x = (v.x - m) * is * g + bb; r.y = (v.y - m) * is * g + bb;
        r.z = (v.z - m) * is * g + bb; r.w = (v.w - m) * is * g + bb;
        if (p4) { float4 q = p4[p]; r.x += q.x; r.y += q.y; r.z += q.z; r.w += q.w; }
        d4[p] = r;
    }
}

// -------- fused IN1(fno+x) -> att, IN2(att) -> an
__global__ void k_norm12(const float* __restrict__ fno, const float* __restrict__ x,
                         float* __restrict__ att, float* __restrict__ an,
                         const float* __restrict__ gA, const float* __restrict__ bA) {
    int img = blockIdx.x, tid = threadIdx.x;
    const float4* f4 = (const float4*)(fno + (size_t)img * HW);
    const float4* x4 = (const float4*)(x + (size_t)img * HW);
    float4* att4 = (float4*)(att + (size_t)img * HW);
    float4* an4  = (float4*)(an + (size_t)img * HW);
    float sum = 0.f, sq = 0.f;
    for (int p = tid; p < 4096; p += 512) {
        float4 v = f4[p], a = x4[p];
        v.x += a.x; v.y += a.y; v.z += a.z; v.w += a.w;
        sum += v.x + v.y + v.z + v.w;
        sq += v.x * v.x + v.y * v.y + v.z * v.z + v.w * v.w;
    }
    __shared__ float shm[34];
    float m, is1;
    block_stats(sum, sq, shm, m, is1);
    __shared__ float is2_s;
    if (tid == 0) {
        float g1 = gA[1];
        float var = 1.f / (is1 * is1) - 1e-5f;
        float varatt = g1 * g1 * var * is1 * is1;
        is2_s = rsqrtf(varatt + 1e-5f);
    }
    __syncthreads();
    float g1 = gA[1], b1 = bA[1], g2 = gA[2], b2 = bA[2], is2 = is2_s;
    for (int p = tid; p < 4096; p += 512) {
        float4 v = f4[p], a = x4[p];
        v.x += a.x; v.y += a.y; v.z += a.z; v.w += a.w;
        float4 r, n;
        r.x = (v.x - m) * is1 * g1 + b1; r.y = (v.y - m) * is1 * g1 + b1;
        r.z = (v.z - m) * is1 * g1 + b1; r.w = (v.w - m) * is1 * g1 + b1;
        n.x = (r.x - b1) * is2 * g2 + b2; n.y = (r.y - b1) * is2 * g2 + b2;
        n.z = (r.z - b1) * is2 * g2 + b2; n.w = (r.w - b1) * is2 * g2 + b2;
        att4[p] = r; an4[p] = n;
    }
}

__device__ __forceinline__ float gelu1(float v) {
    return 0.5f * v * (1.f + erff(v * 0.70710678118654752f));
}

// -------- fused IN(gi)(src) then dst = [gelu](norm + ws*src2 + bs)
__global__ void k_normeps(const float* __restrict__ src, const float* __restrict__ src2,
                          float* __restrict__ dst, const float* __restrict__ gA,
                          const float* __restrict__ bA, int gi,
                          const float* __restrict__ ws, const float* __restrict__ bs,
                          int dogelu) {
    int img = blockIdx.x, tid = threadIdx.x;
    const float4* s4 = (const float4*)(src + (size_t)img * HW);
    const float4* s24 = (const float4*)(src2 + (size_t)img * HW);
    float4* d4 = (float4*)(dst + (size_t)img * HW);
    float sum = 0.f, sq = 0.f;
    for (int p = tid; p < 4096; p += 512) {
        float4 v = s4[p];
        sum += v.x + v.y + v.z + v.w;
        sq += v.x * v.x + v.y * v.y + v.z * v.z + v.w * v.w;
    }
    __shared__ float shm[34];
    float m, is;
    block_stats(sum, sq, shm, m, is);
    float g = gA[gi], bb = bA[gi], wsv = ws[0], bsv = bs[0];
    for (int p = tid; p < 4096; p += 512) {
        float4 v = s4[p], a = s24[p], r;
        r.x = (v.x - m) * is * g + bb + wsv * a.x + bsv;
        r.y = (v.y - m) * is * g + bb + wsv * a.y + bsv;
        r.z = (v.z - m) * is * g + bb + wsv * a.z + bsv;
        r.w = (v.w - m) * is * g + bb + wsv * a.w + bsv;
        if (dogelu) { r.x = gelu1(r.x); r.y = gelu1(r.y); r.z = gelu1(r.z); r.w = gelu1(r.w); }
        d4[p] = r;
    }
}

// -------- fwd stage1 (cols); 4-row batching, twiddle recurrence
template <int NC>
__global__ void k_fwd1(const float* __restrict__ x, float* __restrict__ out) {
    int n = blockIdx.x, hb = blockIdx.y;
    __shared__ float xs[32 * 128];
    __shared__ float cs[128], ss[128];
    load_tables(cs, ss);
    for (int t = threadIdx.x; t < 32 * 128; t += blockDim.x)
        xs[t] = x[((size_t)n * 128 + hb * 32) * 128 + t];
    __syncthreads();
    int t = threadIdx.x;
    if (t >= 8 * NC) return;
    int hg = t / NC, c = t % NC;
    float rr[4] = {0, 0, 0, 0}, ii[4] = {0, 0, 0, 0};
    float wr = 1.f, wi = 0.f;
    float str = cs[c], sti = -ss[c];
    #pragma unroll 4
    for (int w = 0; w < 128; w++) {
        #pragma unroll
        for (int kk = 0; kk < 4; kk++) {
            float v = xs[(hg * 4 + kk) * 128 + w];
            rr[kk] += v * wr; ii[kk] += v * wi;
        }
        float nwr = wr * str - wi * sti;
        wi = wr * sti + wi * str;
        wr = nwr;
    }
    #pragma unroll
    for (int kk = 0; kk < 4; kk++) {
        int row = hb * 32 + hg * 4 + kk;
        size_t o = ((size_t)(n * 128 + row) * NC + c) * 2;
        out[o] = rr[kk] * (1.f / 128.f); out[o + 1] = ii[kk] * (1.f / 128.f);
    }
}

// -------- fwd stage2 (rows); c-chunked, twiddle recurrence
__global__ void k_fwd2(const float* __restrict__ F1, float* __restrict__ F2o, int NC) {
    int n = blockIdx.x;
    int chunk = (NC + gridDim.y - 1) / gridDim.y;
    int c0 = blockIdx.y * chunk;
    int cn = NC - c0 < chunk ? NC - c0 : chunk;
    __shared__ float fs[128 * 9 * 2];
    __shared__ float cs[128], ss[128];
    load_tables(cs, ss);
    for (int t = threadIdx.x; t < 128 * cn * 2; t += blockDim.x) {
        int h = t / (cn * 2), rem = t % (cn * 2);
        fs[t] = F1[((size_t)(n * 128 + h) * NC + c0) * 2 + rem];
    }
    __syncthreads();
    int tid = threadIdx.x;
    if (tid >= 64 * cn) return;
    int jr = tid / cn, cl = tid % cn;
    int r = jr < 32 ? jr : jr + 64;
    float wr = 1.f, wi = 0.f;
    float str = cs[r & 127], sti = -ss[r & 127];
    float re = 0.f, im = 0.f;
    #pragma unroll 4
    for (int h = 0; h < 128; h++) {
        float ar = fs[(h * cn + cl) * 2], ai = fs[(h * cn + cl) * 2 + 1];
        re += ar * wr - ai * wi;
        im += ar * wi + ai * wr;
        float nwr = wr * str - wi * sti;
        wi = wr * sti + wi * str;
        wr = nwr;
    }
    size_t oo = ((size_t)(n * 64 + jr) * NC + c0 + cl) * 2;
    F2o[oo] = re * (1.f / 128.f); F2o[oo + 1] = im * (1.f / 128.f);
}

// -------- fused inverse (row+col), optional weight mult, partial sums, pixel add
__global__ void k_inv2(const float* __restrict__ src, const float* __restrict__ wmul,
                       float* __restrict__ dst, int NC, int P, const float* __restrict__ yadd,
                       int nparts, size_t pstride) {
    int n = blockIdx.x;
    int ybase = blockIdx.y * 32;
    __shared__ float fs[64 * 33 * 2];
    __shared__ float rr[32 * 33 * 2];
    __shared__ float cs[128], ss[128];
    load_tables(cs, ss);
    for (int t = threadIdx.x; t < 64 * NC; t += blockDim.x) {
        int jj = t / NC, c = t % NC;
        size_t base = ((size_t)n * 64 * NC + t) * 2;
        float ar = 0.f, ai = 0.f;
        for (int p = 0; p < nparts; p++) {
            ar += src[p * pstride + base];
            ai += src[p * pstride + base + 1];
        }
        if (wmul) {
            int sgn = jj < 32 ? 0 : 1, jjm = jj & 31;
            const float* wp = wmul + (((size_t)sgn * 32 + jjm) * 32 + c) * 2;
            float wr = wp[0], wi = wp[1];
            float r2 = ar * wr - ai * wi, i2 = ar * wi + ai * wr;
            ar = r2; ai = i2;
        }
        fs[t * 2] = ar; fs[t * 2 + 1] = ai;
    }
    __syncthreads();
    int step = 128 / P;
    int CG = (NC + 3) >> 2;
    for (int t = threadIdx.x; t < 32 * CG; t += blockDim.x) {
        int yl = t / CG, cg = t % CG;
        int y = ybase + yl, c0 = cg * 4;
        float accr[4] = {0, 0, 0, 0}, acci[4] = {0, 0, 0, 0};
        int ys = (y * step) & 127;
        float stwr = cs[ys], stwi = ss[ys];
        float wr = 1.f, wi = 0.f;
        #pragma unroll 4
        for (int jr = 0; jr < 64; jr++) {
            if (jr == 32) {
                int a = ((P - 32) * y * step) & 127;
                wr = cs[a]; wi = ss[a];
            }
            #pragma unroll
            for (int cc = 0; cc < 4; cc++) {
                if (c0 + cc < NC) {
                    float ar = fs[(jr * NC + c0 + cc) * 2], ai = fs[(jr * NC + c0 + cc) * 2 + 1];
                    accr[cc] += ar * wr - ai * wi;
                    acci[cc] += ar * wi + ai * wr;
                }
            }
            float nwr = wr * stwr - wi * stwi;
            wi = wr * stwi + wi * stwr;
            wr = nwr;
        }
        #pragma unroll
        for (int cc = 0; cc < 4; cc++) {
            if (c0 + cc < NC) {
                rr[(yl * NC + c0 + cc) * 2] = accr[cc];
                rr[(yl * NC + c0 + cc) * 2 + 1] = acci[cc];
            }
        }
    }
    __syncthreads();
    int nyq = ((NC - 1) * 2 == P) ? 1 : 0;
    int cmax = nyq ? NC - 1 : NC;
    int PP = P * P;
    int slots = 8 * P;
    for (int t = threadIdx.x; t < slots; t += blockDim.x) {
        int x = t % P, yg = t / P;
        int yl0 = yg * 4;
        float acc[4];
        #pragma unroll
        for (int yy = 0; yy < 4; yy++) acc[yy] = rr[((yl0 + yy) * NC) * 2];
        int xs_ = (x * step) & 127;
        float stwr = cs[xs_], stwi = ss[xs_];
        float wr = stwr, wi = stwi;
        #pragma unroll 4
        for (int c = 1; c < cmax; c++) {
            #pragma unroll
            for (int yy = 0; yy < 4; yy++) {
                float re = rr[((yl0 + yy) * NC + c) * 2], im = rr[((yl0 + yy) * NC + c) * 2 + 1];
                acc[yy] += 2.f * (re * wr - im * wi);
            }
            float nwr = wr * stwr - wi * stwi;
            wi = wr * stwi + wi * stwr;
            wr = nwr;
        }
        if (nyq) {
            #pragma unroll
            for (int yy = 0; yy < 4; yy++)
                acc[yy] += rr[((yl0 + yy) * NC + NC - 1) * 2] * wr;
        }
        #pragma unroll
        for (int yy = 0; yy < 4; yy++) {
            int p = (ybase + yl0 + yy) * P + x;
            float v = acc[yy];
            if (yadd) v += yadd[(size_t)n * PP + p];
            dst[(size_t)n * PP + p] = v;
        }
    }
}

// -------- mode-space Qhat/Khat: Qof = ws*F2 + spec + bs*delta, symmetrize cols 0/32
__device__ __forceinline__ void qof_eval(const float* __restrict__ f2s,
                                         const float* __restrict__ w, int h, int y, int c,
                                         float wsv, float bsv, float& vr, float& vi) {
    float fr = f2s[(y * 33 + c) * 2], fi = f2s[(y * 33 + c) * 2 + 1];
    vr = wsv * fr; vi = wsv * fi;
    if (y == 0 && c == 0) vr += bsv;
    if (c < 16 && (y < 16 || y >= 48)) {
        int sgn = y < 16 ? 0 : 1, jm = y < 16 ? y : y - 48;
        const float* wp = w + (((size_t)(sgn * 32 + h) * 16 + jm) * 16 + c) * 2;
        float wr = wp[0], wi = wp[1];
        vr += fr * wr - fi * wi;
        vi += fr * wi + fi * wr;
    }
}

__global__ void k_qkhat(const float* __restrict__ F2,
                        const float* __restrict__ wKp, const float* __restrict__ wsK,
                        const float* __restrict__ bsK,
                        const float* __restrict__ wQp, const float* __restrict__ wsQ,
                        const float* __restrict__ bsQ,
                        float* __restrict__ kh, float* __restrict__ qh) {
    int i = blockIdx.x, z = blockIdx.y;    // z=0: K (weighted), z=1: Q
    const float* w = z ? wQp : wKp;
    const float* wsA = z ? wsQ : wsK;
    const float* bsA = z ? bsQ : bsK;
    float* dst = z ? qh : kh;
    __shared__ float f2s[64 * 33 * 2];
    for (int t = threadIdx.x; t < 64 * 33 * 2; t += blockDim.x)
        f2s[t] = F2[(size_t)i * (64 * 33 * 2) + t];
    __syncthreads();
    for (int t = threadIdx.x; t < 32 * 2112; t += blockDim.x) {
        int h = t / 2112, m = t % 2112;
        int y = m / 33, c = m % 33;
        float wsv = wsA[h], bsv = bsA[h];
        float vr, vi;
        qof_eval(f2s, w, h, y, c, wsv, bsv, vr, vi);
        if (c == 0 || c == 32) {
            int ym = (64 - y) & 63;
            float mr, mi;
            qof_eval(f2s, w, h, ym, c, wsv, bsv, mr, mi);
            vr = 0.5f * (vr + mr);
            vi = 0.5f * (vi - mi);
        }
        if (z == 0) {
            float wc = (c == 0 || c == 32) ? 1.f : 2.f;
            vr *= wc; vi *= wc;
        }
        size_t oo = ((size_t)(i * 32 + h) * 2112 + m) * 2;
        dst[oo] = vr; dst[oo + 1] = vi;
    }
}

// -------- scores partials over mode-chunks; grid (64, 11); d=4224
__global__ void k_scores_part(const float* __restrict__ q, const float* __restrict__ k,
                              float* __restrict__ scp) {
    int bh = blockIdx.x, b = bh >> 5, h = bh & 31;
    int ch = blockIdx.y;
    int tid = threadIdx.x;
    int ti = tid >> 4, si = tid & 15;
    __shared__ float qs_[32 * 132], ks_[32 * 132];
    float a00 = 0.f, a01 = 0.f, a10 = 0.f, a11 = 0.f;
    for (int kk = ch * 384; kk < ch * 384 + 384; kk += 128) {
        __syncthreads();
        for (int t = tid; t < 4096; t += 256) {
            int row = t >> 7, col = t & 127;
            size_t base = (size_t)((b * 32 + row) * 32 + h) * 4224 + kk + col;
            qs_[row * 132 + col] = q[base];
            ks_[row * 132 + col] = k[base];
        }
        __syncthreads();
        #pragma unroll 4
        for (int j = 0; j < 128; j++) {
            float q0 = qs_[(2 * ti) * 132 + j], q1 = qs_[(2 * ti + 1) * 132 + j];
            float k0 = ks_[(2 * si) * 132 + j], k1 = ks_[(2 * si + 1) * 132 + j];
            a00 += q0 * k0; a01 += q0 * k1; a10 += q1 * k0; a11 += q1 * k1;
        }
    }
    float* sp = scp + ((size_t)ch * 64 + bh) * 1024;
    sp[(2 * ti) * 32 + 2 * si]         = a00;
    sp[(2 * ti) * 32 + 2 * si + 1]     = a01;
    sp[(2 * ti + 1) * 32 + 2 * si]     = a10;
    sp[(2 * ti + 1) * 32 + 2 * si + 1] = a11;
}

// -------- combine partials + softmax; scale = 64 (Parseval factor / sqrt(d) / temp)
__global__ void k_softmax(const float* __restrict__ scp, float* __restrict__ attn) {
    int bh = blockIdx.x, tid = threadIdx.x;
    float v = 0.f;
    #pragma unroll
    for (int c = 0; c < 11; c++) v += scp[((size_t)c * 64 + bh) * 1024 + tid];
    v *= 64.f;
    float mx = v;
    for (int o = 16; o > 0; o >>= 1) mx = fmaxf(mx, __shfl_xor_sync(0xffffffffu, mx, o));
    float e = expf(v - mx), sm = e;
    for (int o = 16; o > 0; o >>= 1) sm += __shfl_xor_sync(0xffffffffu, sm, o);
    attn[(size_t)bh * 1024 + tid] = e / sm;
}

// -------- Vhat + SpecVhat
__global__ void k_vhat(const float* __restrict__ F2, const float* __restrict__ wV,
                       const float* __restrict__ wVs, const float* __restrict__ bVs,
                       float* __restrict__ vhat, float* __restrict__ svhat) {
    int i = blockIdx.x, h = blockIdx.y;
    __shared__ float f2s[64 * 33 * 2];
    __shared__ float wv_s[1024];
    for (int t = threadIdx.x; t < 64 * 33 * 2; t += blockDim.x)
        f2s[t] = F2[(size_t)i * (64 * 33 * 2) + t];
    for (int t = threadIdx.x; t < 1024; t += blockDim.x) {
        int sgn = t >> 9;
        wv_s[t] = wV[((size_t)(sgn * 32 + h) * 256) * 2 + (t & 511)];
    }
    __syncthreads();
    float wvsv = wVs[h], bvsv = bVs[h];

    #define OF(JJ, CC, ORR, OII) { int sg_ = (JJ) < 16 ? 0 : 1; int jm_ = (JJ) < 16 ? (JJ) : (JJ) - 48; \
        float fr_ = f2s[((JJ) * 33 + (CC)) * 2], fi_ = f2s[((JJ) * 33 + (CC)) * 2 + 1]; \
        float wr_ = wv_s[sg_ * 512 + (jm_ * 16 + (CC)) * 2], wi_ = wv_s[sg_ * 512 + (jm_ * 16 + (CC)) * 2 + 1]; \
        ORR = fr_ * wr_ - fi_ * wi_; OII = fr_ * wi_ + fi_ * wr_; }

    for (int t = threadIdx.x; t < 2048; t += blockDim.x) {
        int jj = t >> 5, c = t & 31;
        float fr = f2s[(jj * 33 + c) * 2], fi = f2s[(jj * 33 + c) * 2 + 1];
        float vr = wvsv * fr, vi = wvsv * fi;
        if (jj == 0 && c == 0) vr += bvsv;
        if (c >= 1 && c < 16 && (jj < 16 || jj >= 48)) {
            float orr, oii; OF(jj, c, orr, oii);
            vr += orr; vi += oii;
        } else if (c == 0) {
            if (jj == 0) {
                float orr, oii; OF(0, 0, orr, oii); (void)oii;
                vr += orr;
            } else if (jj <= 15) {
                float o1r, o1i, o2r, o2i;
                OF(jj, 0, o1r, o1i); OF(64 - jj, 0, o2r, o2i);
                vr += 0.5f * (o1r + o2r); vi += 0.5f * (o1i - o2i);
            } else if (jj == 16) {
                float orr, oii; OF(48, 0, orr, oii);
                vr += 0.5f * orr; vi -= 0.5f * oii;
            } else if (jj == 48) {
                float orr, oii; OF(48, 0, orr, oii);
                vr += 0.5f * orr; vi += 0.5f * oii;
            } else if (jj >= 49) {
                float o1r, o1i, o2r, o2i;
                OF(jj, 0, o1r, o1i); OF(64 - jj, 0, o2r, o2i);
                vr += 0.5f * (o1r + o2r); vi += 0.5f * (o1i - o2i);
            }
        }
        size_t oo = ((size_t)(i * 32 + h) * 2048 + t) * 2;
        vhat[oo] = vr; vhat[oo + 1] = vi;
    }
    for (int t = threadIdx.x; t < 512; t += blockDim.x) {
        int jm = t >> 4, c = t & 15;
        int jj = jm < 16 ? jm : jm + 32;
        float orr, oii; OF(jj, c, orr, oii);
        size_t oo = ((size_t)(i * 32 + h) * 512 + t) * 2;
        svhat[oo] = orr; svhat[oo + 1] = oii;
    }
    #undef OF
}

// -------- sghat = attn x svhat
__global__ void k_ghat(const float* __restrict__ attn, const float* __restrict__ vin,
                       float* __restrict__ gout, int ncols) {
    int b = blockIdx.x, h = blockIdx.y, c0 = blockIdx.z * 256;
    __shared__ float a_sh[1024];
    __shared__ float vs[32 * 256];
    for (int t = threadIdx.x; t < 1024; t += 256)
        a_sh[t] = attn[(size_t)(b * 32 + h) * 1024 + t];
    for (int t = threadIdx.x; t < 8192; t += 256) {
        int s = t >> 8, c = t & 255;
        vs[t] = vin[(size_t)((b * 32 + s) * 32 + h) * ncols + c0 + c];
    }
    __syncthreads();
    int tq = threadIdx.x >> 5;
    int cg = threadIdx.x & 31;
    float acc[4][8];
    #pragma unroll
    for (int r = 0; r < 4; r++)
        #pragma unroll
        for (int cc = 0; cc < 8; cc++) acc[r][cc] = 0.f;
    for (int s = 0; s < 32; s++) {
        float a0 = a_sh[(tq * 4 + 0) * 32 + s];
        float a1 = a_sh[(tq * 4 + 1) * 32 + s];
        float a2 = a_sh[(tq * 4 + 2) * 32 + s];
        float a3 = a_sh[(tq * 4 + 3) * 32 + s];
        const float* vp = vs + s * 256 + cg * 8;
        #pragma unroll
        for (int cc = 0; cc < 8; cc++) {
            float v = vp[cc];
            acc[0][cc] += a0 * v; acc[1][cc] += a1 * v;
            acc[2][cc] += a2 * v; acc[3][cc] += a3 * v;
        }
    }
    #pragma unroll
    for (int r = 0; r < 4; r++)
        #pragma unroll
        for (int cc = 0; cc < 8; cc++)
            gout[(size_t)((b * 32 + tq * 4 + r) * 32 + h) * ncols + c0 + cg * 8 + cc] = acc[r][cc];
}

// -------- fused (attn x vhat) x wP -> PF partials; grid (b=2, mc=16, hg=8)
__global__ void k_gpf(const float* __restrict__ attn, const float* __restrict__ vhat,
                      const float* __restrict__ wP, float* __restrict__ PFp) {
    int b = blockIdx.x, mc = blockIdx.y, hg = blockIdx.z;
    __shared__ float a_sh[1024];
    __shared__ float vs[8192];
    int tid = threadIdx.x;
    int tq = tid >> 5, mg = tid & 31;
    float accr[4][4], acci[4][4];
    #pragma unroll
    for (int r = 0; r < 4; r++)
        #pragma unroll
        for (int m = 0; m < 4; m++) { accr[r][m] = 0.f; acci[r][m] = 0.f; }
    for (int hh = 0; hh < 4; hh++) {
        int h = hg * 4 + hh;
        __syncthreads();
        for (int t = tid; t < 1024; t += 256)
            a_sh[t] = attn[(size_t)(b * 32 + h) * 1024 + t];
        for (int t = tid; t < 8192; t += 256) {
            int s = t >> 8, c = t & 255;
            vs[t] = vhat[((size_t)((b * 32 + s) * 32 + h) * 2048 + mc * 128) * 2 + c];
        }
        __syncthreads();
        float tr[4][4], ti_[4][4];
        #pragma unroll
        for (int r = 0; r < 4; r++)
            #pragma unroll
            for (int m = 0; m < 4; m++) { tr[r][m] = 0.f; ti_[r][m] = 0.f; }
        #pragma unroll 4
        for (int s = 0; s < 32; s++) {
            float a0 = a_sh[(tq * 4 + 0) * 32 + s];
            float a1 = a_sh[(tq * 4 + 1) * 32 + s];
            float a2 = a_sh[(tq * 4 + 2) * 32 + s];
            float a3 = a_sh[(tq * 4 + 3) * 32 + s];
            const float* vp = vs + s * 256 + mg * 8;
            #pragma unroll
            for (int m = 0; m < 4; m++) {
                float vre = vp[m * 2], vim = vp[m * 2 + 1];
                tr[0][m] += a0 * vre; ti_[0][m] += a0 * vim;
                tr[1][m] += a1 * vre; ti_[1][m] += a1 * vim;
                tr[2][m] += a2 * vre; ti_[2][m] += a2 * vim;
                tr[3][m] += a3 * vre; ti_[3][m] += a3 * vim;
            }
        }
        #pragma unroll
        for (int m = 0; m < 4; m++) {
            int M = mc * 128 + mg * 4 + m;
            int jj = M >> 5, c = M & 31;
            int sgn = jj < 32 ? 0 : 1, jjm = jj & 31;
            const float* wp = wP + (((size_t)(sgn * 32 + h) * 32 + jjm) * 32 + c) * 2;
            float wr = wp[0], wi = wp[1];
            #pragma unroll
            for (int r = 0; r < 4; r++) {
                accr[r][m] += tr[r][m] * wr - ti_[r][m] * wi;
                acci[r][m] += tr[r][m] * wi + ti_[r][m] * wr;
            }
        }
    }
    #pragma unroll
    for (int r = 0; r < 4; r++) {
        int i = b * 32 + tq * 4 + r;
        #pragma unroll
        for (int m = 0; m < 4; m++) {
            int M = mc * 128 + mg * 4 + m;
            size_t o = (size_t)hg * (NI * 4096) + (size_t)i * 4096 + (size_t)M * 2;
            PFp[o] = accr[r][m]; PFp[o + 1] = acci[r][m];
        }
    }
}

// -------- window extras into PF partial slot 0
__global__ void k_pfw(const float* __restrict__ sghat, const float* __restrict__ wPs,
                      float* __restrict__ PFp) {
    int i = blockIdx.x;
    int w = blockIdx.y * 256 + threadIdx.x;
    __shared__ float wps_[32];
    if (threadIdx.x < 32) wps_[threadIdx.x] = wPs[threadIdx.x];
    __syncthreads();
    int jm = w >> 4, c = w & 15;
    int jj = jm < 16 ? jm : jm + 32;
    int t = jj * 32 + c;
    float re = 0.f, im = 0.f;
    #pragma unroll 4
    for (int h = 0; h < 32; h++) {
        const float* sg = sghat + ((size_t)(i * 32 + h) * 512 + w) * 2;
        re += wps_[h] * sg[0]; im += wps_[h] * sg[1];
    }
    size_t o = (size_t)i * 4096 + (size_t)t * 2;
    PFp[o] += re; PFp[o + 1] += im;
}

// -------- token mix y2
__global__ void k_tokmix(const float* __restrict__ attn, const float* __restrict__ xan,
                         const float* __restrict__ wPs, const float* __restrict__ wVs,
                         const float* __restrict__ bVs, const float* __restrict__ bPs,
                         float* __restrict__ y2) {
    int b = blockIdx.x;
    int pbase = blockIdx.y * 256;
    int tid = threadIdx.x;
    __shared__ float C[1024];
    __shared__ float xs[32 * 256];
    __shared__ float cb_s;
    {
        int t = tid >> 3, s0 = (tid & 7) * 4;
        float c0 = 0.f, c1 = 0.f, c2 = 0.f, c3 = 0.f;
        for (int h = 0; h < 32; h++) {
            float w = wPs[h] * wVs[h];
            const float* ap = attn + (size_t)(b * 32 + h) * 1024 + t * 32 + s0;
            c0 += w * ap[0]; c1 += w * ap[1]; c2 += w * ap[2]; c3 += w * ap[3];
        }
        C[t * 32 + s0] = c0; C[t * 32 + s0 + 1] = c1;
        C[t * 32 + s0 + 2] = c2; C[t * 32 + s0 + 3] = c3;
    }
    if (tid == 0) {
        float cb = bPs[0];
        for (int h = 0; h < 32; h++) cb += wPs[h] * bVs[h];
        cb_s = cb;
    }
    for (int t = tid; t < 8192; t += 256) {
        int s = t >> 8, c = t & 255;
        xs[t] = xan[(size_t)(b * 32 + s) * HW + pbase + c];
    }
    __syncthreads();
    int t = tid >> 3, pg = tid & 7;
    float acc[32];
    #pragma unroll
    for (int pp = 0; pp < 32; pp++) acc[pp] = 0.f;
    for (int s = 0; s < 32; s++) {
        float cc = C[t * 32 + s];
        const float* xp = xs + s * 256 + pg * 32;
        #pragma unroll
        for (int pp = 0; pp < 32; pp++) acc[pp] += cc * xp[pp];
    }
    float cb = cb_s;
    #pragma unroll
    for (int pp = 0; pp < 32; pp++)
        y2[(size_t)(b * 32 + t) * HW + pbase + pg * 32 + pp] = acc[pp] + cb;
}

extern "C" void kernel_launch(void* const* d_in, const int* in_sizes, int n_in,
                              void* d_out, int out_size) {
    const float* x    = (const float*)d_in[0];
    const float* wK   = (const float*)d_in[1];
    const float* wKs  = (const float*)d_in[2];
    const float* bKs  = (const float*)d_in[3];
    const float* wQ   = (const float*)d_in[4];
    const float* wQs  = (const float*)d_in[5];
    const float* bQs  = (const float*)d_in[6];
    const float* wV   = (const float*)d_in[7];
    const float* wVs  = (const float*)d_in[8];
    const float* bVs  = (const float*)d_in[9];
    const float* wP   = (const float*)d_in[10];
    const float* wPs  = (const float*)d_in[11];
    const float* bPs  = (const float*)d_in[12];
    const float* wM0  = (const float*)d_in[13];
    const float* wM0s = (const float*)d_in[14];
    const float* bM0s = (const float*)d_in[15];
    const float* wM1  = (const float*)d_in[16];
    const float* wM1s = (const float*)d_in[17];
    const float* bM1s = (const float*)d_in[18];
    const float* ng   = (const float*)d_in[19];
    const float* nb   = (const float*)d_in[20];
    float* out = (float*)d_out;

    float *p_xan, *p_F1, *p_F2, *p_qh, *p_kh, *p_scp, *p_attn;
    float *p_vhat, *p_svhat, *p_sghat, *p_PFp, *p_y2;
    float *p_fno, *p_att, *p_an, *p_m, *p_MF1, *p_MF2;
    cudaGetSymbolAddress((void**)&p_xan,   s_xan);
    cudaGetSymbolAddress((void**)&p_F1,    s_F1);
    cudaGetSymbolAddress((void**)&p_F2,    s_F2);
    cudaGetSymbolAddress((void**)&p_qh,    s_qh);
    cudaGetSymbolAddress((void**)&p_kh,    s_kh);
    cudaGetSymbolAddress((void**)&p_scp,   s_scp);
    cudaGetSymbolAddress((void**)&p_attn,  s_attn);
    cudaGetSymbolAddress((void**)&p_vhat,  s_vhat);
    cudaGetSymbolAddress((void**)&p_svhat, s_svhat);
    cudaGetSymbolAddress((void**)&p_sghat, s_sghat);
    cudaGetSymbolAddress((void**)&p_PFp,   s_PFp);
    cudaGetSymbolAddress((void**)&p_y2,    s_y2);
    cudaGetSymbolAddress((void**)&p_fno,   s_fno);
    cudaGetSymbolAddress((void**)&p_att,   s_att);
    cudaGetSymbolAddress((void**)&p_an,    s_an);
    cudaGetSymbolAddress((void**)&p_m,     s_m);
    cudaGetSymbolAddress((void**)&p_MF1,   s_MF1);
    cudaGetSymbolAddress((void**)&p_MF2,   s_MF2);

    const size_t PSTRIDE = (size_t)NI * 4096;

    k_init<<<1, 128>>>();

    // xa_n (idx0) + partial spectrum
    k_inorm<<<NI, 512>>>(x, nullptr, p_xan, ng, nb, 0, nullptr);
    k_fwd1<33><<<dim3(NI, 4), 264>>>(p_xan, p_F1);
    k_fwd2<<<dim3(NI, 4), 576>>>(p_F1, p_F2, 33);

    // mode-space Qhat / Khat (skip + spec + bias, Parseval-symmetrized)
    k_qkhat<<<dim3(NI, 2), 512>>>(p_F2, wK, wKs, bKs, wQ, wQs, bQs, p_kh, p_qh);

    // attention weights (mode-space scores, d=4224)
    k_scores_part<<<dim3(64, 11), 256>>>(p_qh, p_kh, p_scp);
    k_softmax<<<64, 1024>>>(p_scp, p_attn);

    // mode-space V / attention / projection
    k_vhat<<<dim3(NI, NH), 256>>>(p_F2, wV, wVs, bVs, p_vhat, p_svhat);
    k_ghat<<<dim3(2, 32, 4), 256>>>(p_attn, p_svhat, p_sghat, 1024);
    k_gpf<<<dim3(2, 16, 8), 256>>>(p_attn, p_vhat, wP, p_PFp);
    k_pfw<<<dim3(NI, 2), 256>>>(p_sghat, wPs, p_PFp);
    k_tokmix<<<dim3(2, 64), 256>>>(p_attn, p_xan, wPs, wVs, bVs, bPs, p_y2);
    k_inv2<<<dim3(NI, 4), 512>>>(p_PFp, nullptr, p_fno, 32, 128, p_y2, 8, PSTRIDE);

    // att = IN1(projd + xa); an = IN2(att)
    k_norm12<<<NI, 512>>>(p_fno, x, p_att, p_an, ng, nb);

    // mixer layer 0 (idx3 + gelu)
    k_fwd1<32><<<dim3(NI, 4), 256>>>(p_an, p_MF1);
    k_fwd2<<<dim3(NI, 4), 512>>>(p_MF1, p_MF2, 32);
    k_inv2<<<dim3(NI, 4), 512>>>(p_MF2, wM0, p_fno, 32, 128, nullptr, 1, 0);
    k_normeps<<<NI, 512>>>(p_fno, p_an, p_m, ng, nb, 3, wM0s, bM0s, 1);

    // mixer layer 1 (idx4)
    k_fwd1<32><<<dim3(NI, 4), 256>>>(p_m, p_MF1);
    k_fwd2<<<dim3(NI, 4), 512>>>(p_MF1, p_MF2, 32);
    k_inv2<<<dim3(NI, 4), 512>>>(p_MF2, wM1, p_fno, 32, 128, nullptr, 1, 0);
    k_normeps<<<NI, 512>>>(p_fno, p_m, p_m, ng, nb, 4, wM1s, bM1s, 0);

    // output = IN5(m) + att
    k_inorm<<<NI, 512>>>(p_m, nullptr, out, ng, nb, 5, p_att);
}

// round 13
// speedup vs baseline: 1.5321x; 1.5321x over previous
#include <cuda_runtime.h>
#include <cuda_bf16.h>
#include <cstdint>
#include <cstddef>

#define NI 64
#define NH 32
#define HW 16384

__device__ float d_c[128];
__device__ float d_s[128];

__device__ float s_xan [NI*HW];
__device__ float s_F1  [NI*128*33*2];
__device__ float s_F2  [NI*64*33*2];
__device__ float s_R64 [NI*64*64];
__device__ float s_k   [(size_t)NI*NH*64*64];
__device__ float s_q   [(size_t)NI*NH*64*64];
__device__ float s_scp [8*64*1024];
__device__ float s_attn[64*1024];
__device__ float s_vhat [(size_t)NI*NH*4096];
__device__ float s_svhat[(size_t)NI*NH*1024];
__device__ float s_sghat[(size_t)NI*NH*1024];
__device__ float s_PFp [(size_t)8*NI*4096];
__device__ float s_y2  [NI*HW];
__device__ float s_fno [NI*HW];
__device__ float s_att [NI*HW];
__device__ float s_an  [NI*HW];
__device__ float s_m   [NI*HW];
__device__ float s_MF1 [NI*128*32*2];
__device__ float s_MF2 [NI*64*32*2];

__device__ __forceinline__ void load_tables(float* cs, float* ss) {
    for (int t = threadIdx.x; t < 128; t += blockDim.x) { cs[t] = d_c[t]; ss[t] = d_s[t]; }
}

__global__ void k_init() {
    int k = threadIdx.x;
    d_c[k] = cospif(k / 64.0f);
    d_s[k] = sinpif(k / 64.0f);
}

// block stats via warp shuffles; 512 threads
__device__ __forceinline__ void block_stats(float sum, float sq, float* shm,
                                            float& mean, float& istd) {
    #pragma unroll
    for (int o = 16; o; o >>= 1) {
        sum += __shfl_xor_sync(0xffffffffu, sum, o);
        sq  += __shfl_xor_sync(0xffffffffu, sq, o);
    }
    int wid = threadIdx.x >> 5;
    if ((threadIdx.x & 31) == 0) { shm[wid] = sum; shm[16 + wid] = sq; }
    __syncthreads();
    if (threadIdx.x < 32) {
        float a = (threadIdx.x < 16) ? shm[threadIdx.x] : 0.f;
        float b = (threadIdx.x < 16) ? shm[16 + threadIdx.x] : 0.f;
        #pragma unroll
        for (int o = 8; o; o >>= 1) {
            a += __shfl_xor_sync(0xffffffffu, a, o);
            b += __shfl_xor_sync(0xffffffffu, b, o);
        }
        if (threadIdx.x == 0) {
            float m = a * (1.f / HW);
            float var = b * (1.f / HW) - m * m;
            shm[32] = m; shm[33] = rsqrtf(var + 1e-5f);
        }
    }
    __syncthreads();
    mean = shm[32]; istd = shm[33];
}

// -------- instance norm (512 thr, float4); optional pre-add & post-add
__global__ void k_inorm(const float* __restrict__ src, const float* __restrict__ add,
                        float* __restrict__ dst, const float* __restrict__ gA,
                        const float* __restrict__ bA, int gi, const float* __restrict__ post) {
    int img = blockIdx.x, tid = threadIdx.x;
    const float4* s4 = (const float4*)(src + (size_t)img * HW);
    const float4* a4 = add ? (const float4*)(add + (size_t)img * HW) : nullptr;
    const float4* p4 = post ? (const float4*)(post + (size_t)img * HW) : nullptr;
    float4* d4 = (float4*)(dst + (size_t)img * HW);
    float sum = 0.f, sq = 0.f;
    for (int p = tid; p < 4096; p += 512) {
        float4 v = s4[p];
        if (a4) { float4 a = a4[p]; v.x += a.x; v.y += a.y; v.z += a.z; v.w += a.w; }
        sum += v.x + v.y + v.z + v.w;
        sq += v.x * v.x + v.y * v.y + v.z * v.z + v.w * v.w;
    }
    __shared__ float shm[34];
    float m, is;
    block_stats(sum, sq, shm, m, is);
    float g = gA[gi], bb = bA[gi];
    for (int p = tid; p < 4096; p += 512) {
        float4 v = s4[p];
        if (a4) { float4 a = a4[p]; v.x += a.x; v.y += a.y; v.z += a.z; v.w += a.w; }
        float4 r;
        r.x = (v.x - m) * is * g + bb; r.y = (v.y - m) * is * g + bb;
        r.z = (v.z - m) * is * g + bb; r.w = (v.w - m) * is * g + bb;
        if (p4) { float4 q = p4[p]; r.x += q.x; r.y += q.y; r.z += q.z; r.w += q.w; }
        d4[p] = r;
    }
}

// -------- fused IN1(fno+x) -> att, IN2(att) -> an
__global__ void k_norm12(const float* __restrict__ fno, const float* __restrict__ x,
                         float* __restrict__ att, float* __restrict__ an,
                         const float* __restrict__ gA, const float* __restrict__ bA) {
    int img = blockIdx.x, tid = threadIdx.x;
    const float4* f4 = (const float4*)(fno + (size_t)img * HW);
    const float4* x4 = (const float4*)(x + (size_t)img * HW);
    float4* att4 = (float4*)(att + (size_t)img * HW);
    float4* an4  = (float4*)(an + (size_t)img * HW);
    float sum = 0.f, sq = 0.f;
    for (int p = tid; p < 4096; p += 512) {
        float4 v = f4[p], a = x4[p];
        v.x += a.x; v.y += a.y; v.z += a.z; v.w += a.w;
        sum += v.x + v.y + v.z + v.w;
        sq += v.x * v.x + v.y * v.y + v.z * v.z + v.w * v.w;
    }
    __shared__ float shm[34];
    float m, is1;
    block_stats(sum, sq, shm, m, is1);
    __shared__ float is2_s;
    if (tid == 0) {
        float g1 = gA[1];
        float var = 1.f / (is1 * is1) - 1e-5f;
        float varatt = g1 * g1 * var * is1 * is1;
        is2_s = rsqrtf(varatt + 1e-5f);
    }
    __syncthreads();
    float g1 = gA[1], b1 = bA[1], g2 = gA[2], b2 = bA[2], is2 = is2_s;
    for (int p = tid; p < 4096; p += 512) {
        float4 v = f4[p], a = x4[p];
        v.x += a.x; v.y += a.y; v.z += a.z; v.w += a.w;
        float4 r, n;
        r.x = (v.x - m) * is1 * g1 + b1; r.y = (v.y - m) * is1 * g1 + b1;
        r.z = (v.z - m) * is1 * g1 + b1; r.w = (v.w - m) * is1 * g1 + b1;
        n.x = (r.x - b1) * is2 * g2 + b2; n.y = (r.y - b1) * is2 * g2 + b2;
        n.z = (r.z - b1) * is2 * g2 + b2; n.w = (r.w - b1) * is2 * g2 + b2;
        att4[p] = r; an4[p] = n;
    }
}

__device__ __forceinline__ float gelu1(float v) {
    return 0.5f * v * (1.f + erff(v * 0.70710678118654752f));
}

// -------- fused IN(gi)(src) then dst = [gelu](norm + ws*src2 + bs)
__global__ void k_normeps(const float* __restrict__ src, const float* __restrict__ src2,
                          float* __restrict__ dst, const float* __restrict__ gA,
                          const float* __restrict__ bA, int gi,
                          const float* __restrict__ ws, const float* __restrict__ bs,
                          int dogelu) {
    int img = blockIdx.x, tid = threadIdx.x;
    const float4* s4 = (const float4*)(src + (size_t)img * HW);
    const float4* s24 = (const float4*)(src2 + (size_t)img * HW);
    float4* d4 = (float4*)(dst + (size_t)img * HW);
    float sum = 0.f, sq = 0.f;
    for (int p = tid; p < 4096; p += 512) {
        float4 v = s4[p];
        sum += v.x + v.y + v.z + v.w;
        sq += v.x * v.x + v.y * v.y + v.z * v.z + v.w * v.w;
    }
    __shared__ float shm[34];
    float m, is;
    block_stats(sum, sq, shm, m, is);
    float g = gA[gi], bb = bA[gi], wsv = ws[0], bsv = bs[0];
    for (int p = tid; p < 4096; p += 512) {
        float4 v = s4[p], a = s24[p], r;
        r.x = (v.x - m) * is * g + bb + wsv * a.x + bsv;
        r.y = (v.y - m) * is * g + bb + wsv * a.y + bsv;
        r.z = (v.z - m) * is * g + bb + wsv * a.z + bsv;
        r.w = (v.w - m) * is * g + bb + wsv * a.w + bsv;
        if (dogelu) { r.x = gelu1(r.x); r.y = gelu1(r.y); r.z = gelu1(r.z); r.w = gelu1(r.w); }
        d4[p] = r;
    }
}

// -------- fwd stage1 (cols); 4-row batching, twiddle recurrence
template <int NC>
__global__ void k_fwd1(const float* __restrict__ x, float* __restrict__ out) {
    int n = blockIdx.x, hb = blockIdx.y;
    __shared__ float xs[32 * 128];
    __shared__ float cs[128], ss[128];
    load_tables(cs, ss);
    for (int t = threadIdx.x; t < 32 * 128; t += blockDim.x)
        xs[t] = x[((size_t)n * 128 + hb * 32) * 128 + t];
    __syncthreads();
    int t = threadIdx.x;
    if (t >= 8 * NC) return;
    int hg = t / NC, c = t % NC;
    float rr[4] = {0, 0, 0, 0}, ii[4] = {0, 0, 0, 0};
    float wr = 1.f, wi = 0.f;
    float str = cs[c], sti = -ss[c];
    #pragma unroll 4
    for (int w = 0; w < 128; w++) {
        #pragma unroll
        for (int kk = 0; kk < 4; kk++) {
            float v = xs[(hg * 4 + kk) * 128 + w];
            rr[kk] += v * wr; ii[kk] += v * wi;
        }
        float nwr = wr * str - wi * sti;
        wi = wr * sti + wi * str;
        wr = nwr;
    }
    #pragma unroll
    for (int kk = 0; kk < 4; kk++) {
        int row = hb * 32 + hg * 4 + kk;
        size_t o = ((size_t)(n * 128 + row) * NC + c) * 2;
        out[o] = rr[kk] * (1.f / 128.f); out[o + 1] = ii[kk] * (1.f / 128.f);
    }
}

// -------- fwd stage2 (rows); c-chunked, twiddle recurrence
__global__ void k_fwd2(const float* __restrict__ F1, float* __restrict__ F2o, int NC) {
    int n = blockIdx.x;
    int chunk = (NC + gridDim.y - 1) / gridDim.y;
    int c0 = blockIdx.y * chunk;
    int cn = NC - c0 < chunk ? NC - c0 : chunk;
    __shared__ float fs[128 * 9 * 2];
    __shared__ float cs[128], ss[128];
    load_tables(cs, ss);
    for (int t = threadIdx.x; t < 128 * cn * 2; t += blockDim.x) {
        int h = t / (cn * 2), rem = t % (cn * 2);
        fs[t] = F1[((size_t)(n * 128 + h) * NC + c0) * 2 + rem];
    }
    __syncthreads();
    int tid = threadIdx.x;
    if (tid >= 64 * cn) return;
    int jr = tid / cn, cl = tid % cn;
    int r = jr < 32 ? jr : jr + 64;
    float wr = 1.f, wi = 0.f;
    float str = cs[r & 127], sti = -ss[r & 127];
    float re = 0.f, im = 0.f;
    #pragma unroll 4
    for (int h = 0; h < 128; h++) {
        float ar = fs[(h * cn + cl) * 2], ai = fs[(h * cn + cl) * 2 + 1];
        re += ar * wr - ai * wi;
        im += ar * wi + ai * wr;
        float nwr = wr * str - wi * sti;
        wi = wr * sti + wi * str;
        wr = nwr;
    }
    size_t oo = ((size_t)(n * 64 + jr) * NC + c0 + cl) * 2;
    F2o[oo] = re * (1.f / 128.f); F2o[oo + 1] = im * (1.f / 128.f);
}

// -------- fused inverse (row+col), optional weight mult, partial sums, pixel add
__global__ void k_inv2(const float* __restrict__ src, const float* __restrict__ wmul,
                       float* __restrict__ dst, int NC, int P, const float* __restrict__ yadd,
                       int nparts, size_t pstride) {
    int n = blockIdx.x;
    int ybase = blockIdx.y * 32;
    __shared__ float fs[64 * 33 * 2];
    __shared__ float rr[32 * 33 * 2];
    __shared__ float cs[128], ss[128];
    load_tables(cs, ss);
    for (int t = threadIdx.x; t < 64 * NC; t += blockDim.x) {
        int jj = t / NC, c = t % NC;
        size_t base = ((size_t)n * 64 * NC + t) * 2;
        float ar = 0.f, ai = 0.f;
        for (int p = 0; p < nparts; p++) {
            ar += src[p * pstride + base];
            ai += src[p * pstride + base + 1];
        }
        if (wmul) {
            int sgn = jj < 32 ? 0 : 1, jjm = jj & 31;
            const float* wp = wmul + (((size_t)sgn * 32 + jjm) * 32 + c) * 2;
            float wr = wp[0], wi = wp[1];
            float r2 = ar * wr - ai * wi, i2 = ar * wi + ai * wr;
            ar = r2; ai = i2;
        }
        fs[t * 2] = ar; fs[t * 2 + 1] = ai;
    }
    __syncthreads();
    int step = 128 / P;
    int CG = (NC + 3) >> 2;
    for (int t = threadIdx.x; t < 32 * CG; t += blockDim.x) {
        int yl = t / CG, cg = t % CG;
        int y = ybase + yl, c0 = cg * 4;
        float accr[4] = {0, 0, 0, 0}, acci[4] = {0, 0, 0, 0};
        int ys = (y * step) & 127;
        float stwr = cs[ys], stwi = ss[ys];
        float wr = 1.f, wi = 0.f;
        #pragma unroll 4
        for (int jr = 0; jr < 64; jr++) {
            if (jr == 32) {
                int a = ((P - 32) * y * step) & 127;
                wr = cs[a]; wi = ss[a];
            }
            #pragma unroll
            for (int cc = 0; cc < 4; cc++) {
                if (c0 + cc < NC) {
                    float ar = fs[(jr * NC + c0 + cc) * 2], ai = fs[(jr * NC + c0 + cc) * 2 + 1];
                    accr[cc] += ar * wr - ai * wi;
                    acci[cc] += ar * wi + ai * wr;
                }
            }
            float nwr = wr * stwr - wi * stwi;
            wi = wr * stwi + wi * stwr;
            wr = nwr;
        }
        #pragma unroll
        for (int cc = 0; cc < 4; cc++) {
            if (c0 + cc < NC) {
                rr[(yl * NC + c0 + cc) * 2] = accr[cc];
                rr[(yl * NC + c0 + cc) * 2 + 1] = acci[cc];
            }
        }
    }
    __syncthreads();
    int nyq = ((NC - 1) * 2 == P) ? 1 : 0;
    int cmax = nyq ? NC - 1 : NC;
    int PP = P * P;
    int slots = 8 * P;
    for (int t = threadIdx.x; t < slots; t += blockDim.x) {
        int x = t % P, yg = t / P;
        int yl0 = yg * 4;
        float acc[4];
        #pragma unroll
        for (int yy = 0; yy < 4; yy++) acc[yy] = rr[((yl0 + yy) * NC) * 2];
        int xs_ = (x * step) & 127;
        float stwr = cs[xs_], stwi = ss[xs_];
        float wr = stwr, wi = stwi;
        #pragma unroll 4
        for (int c = 1; c < cmax; c++) {
            #pragma unroll
            for (int yy = 0; yy < 4; yy++) {
                float re = rr[((yl0 + yy) * NC + c) * 2], im = rr[((yl0 + yy) * NC + c) * 2 + 1];
                acc[yy] += 2.f * (re * wr - im * wi);
            }
            float nwr = wr * stwr - wi * stwi;
            wi = wr * stwi + wi * stwr;
            wr = nwr;
        }
        if (nyq) {
            #pragma unroll
            for (int yy = 0; yy < 4; yy++)
                acc[yy] += rr[((yl0 + yy) * NC + NC - 1) * 2] * wr;
        }
        #pragma unroll
        for (int yy = 0; yy < 4; yy++) {
            int p = (ybase + yl0 + yy) * P + x;
            float v = acc[yy];
            if (yadd) v += yadd[(size_t)n * PP + p];
            dst[(size_t)n * PP + p] = v;
        }
    }
}

// -------- K/Q fused (z=0 -> K, z=1 -> Q); recurrences in both stages
__global__ void k_kq(const float* __restrict__ F2src,
                     const float* __restrict__ wKp, const float* __restrict__ wQp,
                     const float* __restrict__ R64,
                     const float* __restrict__ wsK, const float* __restrict__ bsK,
                     const float* __restrict__ wsQ, const float* __restrict__ bsQ,
                     float* __restrict__ dstK, float* __restrict__ dstQ) {
    int i = blockIdx.x, o = blockIdx.y, z = blockIdx.z;
    const float* w = z ? wQp : wKp;
    const float* ws = z ? wsQ : wsK;
    const float* bs = z ? bsQ : bsK;
    float* dst = z ? dstQ : dstK;
    __shared__ float fw[32 * 16 * 2];
    __shared__ float rr[64 * 16 * 2];
    __shared__ float cs[128], ss[128];
    load_tables(cs, ss);
    for (int t = threadIdx.x; t < 512; t += blockDim.x) {
        int jj = t >> 4, c = t & 15;
        int jr = jj < 16 ? jj : jj + 32;
        int sgn = jj < 16 ? 0 : 1, jjm = jj & 15;
        float ar = F2src[((size_t)(i * 64 + jr) * 33 + c) * 2];
        float ai = F2src[((size_t)(i * 64 + jr) * 33 + c) * 2 + 1];
        const float* wp = w + (((size_t)(sgn * 32 + o) * 16 + jjm) * 16 + c) * 2;
        float wr = wp[0], wi = wp[1];
        fw[t * 2]     = ar * wr - ai * wi;
        fw[t * 2 + 1] = ar * wi + ai * wr;
    }
    __syncthreads();
    for (int t = threadIdx.x; t < 1024; t += blockDim.x) {
        int y = t >> 4, c = t & 15;
        float re = 0.f, im = 0.f;
        int ys = (y * 2) & 127;
        float stwr = cs[ys], stwi = ss[ys];
        float wr = 1.f, wi = 0.f;
        #pragma unroll
        for (int jj = 0; jj < 32; jj++) {
            if (jj == 16) {
                int a = (48 * y * 2) & 127;
                wr = cs[a]; wi = ss[a];
            }
            float ar = fw[(jj * 16 + c) * 2], ai = fw[(jj * 16 + c) * 2 + 1];
            re += ar * wr - ai * wi;
            im += ar * wi + ai * wr;
            float nwr = wr * stwr - wi * stwi;
            wi = wr * stwi + wi * stwr;
            wr = nwr;
        }
        rr[t * 2] = re; rr[t * 2 + 1] = im;
    }
    __syncthreads();
    float wsv = ws[o], bsv = bs[o];
    size_t obase = (size_t)(i * 32 + o) * 4096;
    for (int t = threadIdx.x; t < 1024; t += blockDim.x) {
        int x = t & 63, yg = t >> 6;
        int y0 = yg * 4;
        float acc[4];
        #pragma unroll
        for (int yy = 0; yy < 4; yy++) acc[yy] = rr[((y0 + yy) * 16) * 2];
        int xs_ = (x * 2) & 127;
        float stwr = cs[xs_], stwi = ss[xs_];
        float wr = stwr, wi = stwi;
        #pragma unroll
        for (int c = 1; c < 16; c++) {
            #pragma unroll
            for (int yy = 0; yy < 4; yy++) {
                float re = rr[((y0 + yy) * 16 + c) * 2], im = rr[((y0 + yy) * 16 + c) * 2 + 1];
                acc[yy] += 2.f * (re * wr - im * wi);
            }
            float nwr = wr * stwr - wi * stwi;
            wi = wr * stwi + wi * stwr;
            wr = nwr;
        }
        #pragma unroll
        for (int yy = 0; yy < 4; yy++) {
            int p = (y0 + yy) * 64 + x;
            dst[obase + p] = acc[yy] + wsv * R64[(size_t)i * 4096 + p] + bsv;
        }
    }
}

// -------- scores partials over d-chunks; grid (64, 8)
__global__ void k_scores_part(const float* __restrict__ q, const float* __restrict__ k,
                              float* __restrict__ scp) {
    int bh = blockIdx.x, b = bh >> 5, h = bh & 31;
    int ch = blockIdx.y;
    int tid = threadIdx.x;
    int ti = tid >> 4, si = tid & 15;
    __shared__ float qs_[32 * 132], ks_[32 * 132];
    float a00 = 0.f, a01 = 0.f, a10 = 0.f, a11 = 0.f;
    for (int kk = ch * 512; kk < ch * 512 + 512; kk += 128) {
        __syncthreads();
        for (int t = tid; t < 4096; t += 256) {
            int row = t >> 7, col = t & 127;
            size_t base = (size_t)((b * 32 + row) * 32 + h) * 4096 + kk + col;
            qs_[row * 132 + col] = q[base];
            ks_[row * 132 + col] = k[base];
        }
        __syncthreads();
        #pragma unroll 4
        for (int j = 0; j < 128; j++) {
            float q0 = qs_[(2 * ti) * 132 + j], q1 = qs_[(2 * ti + 1) * 132 + j];
            float k0 = ks_[(2 * si) * 132 + j], k1 = ks_[(2 * si + 1) * 132 + j];
            a00 += q0 * k0; a01 += q0 * k1; a10 += q1 * k0; a11 += q1 * k1;
        }
    }
    float* sp = scp + ((size_t)ch * 64 + bh) * 1024;
    sp[(2 * ti) * 32 + 2 * si]         = a00;
    sp[(2 * ti) * 32 + 2 * si + 1]     = a01;
    sp[(2 * ti + 1) * 32 + 2 * si]     = a10;
    sp[(2 * ti + 1) * 32 + 2 * si + 1] = a11;
}

// -------- combine partials + softmax
__global__ void k_softmax(const float* __restrict__ scp, float* __restrict__ attn) {
    int bh = blockIdx.x, tid = threadIdx.x;
    float v = 0.f;
    #pragma unroll
    for (int c = 0; c < 8; c++) v += scp[((size_t)c * 64 + bh) * 1024 + tid];
    v *= (1.f / 64.f);
    float mx = v;
    for (int o = 16; o > 0; o >>= 1) mx = fmaxf(mx, __shfl_xor_sync(0xffffffffu, mx, o));
    float e = expf(v - mx), sm = e;
    for (int o = 16; o > 0; o >>= 1) sm += __shfl_xor_sync(0xffffffffu, sm, o);
    attn[(size_t)bh * 1024 + tid] = e / sm;
}

// -------- Vhat + SpecVhat
__global__ void k_vhat(const float* __restrict__ F2, const float* __restrict__ wV,
                       const float* __restrict__ wVs, const float* __restrict__ bVs,
                       float* __restrict__ vhat, float* __restrict__ svhat) {
    int i = blockIdx.x, h = blockIdx.y;
    __shared__ float f2s[64 * 33 * 2];
    __shared__ float wv_s[1024];
    for (int t = threadIdx.x; t < 64 * 33 * 2; t += blockDim.x)
        f2s[t] = F2[(size_t)i * (64 * 33 * 2) + t];
    for (int t = threadIdx.x; t < 1024; t += blockDim.x) {
        int sgn = t >> 9;
        wv_s[t] = wV[((size_t)(sgn * 32 + h) * 256) * 2 + (t & 511)];
    }
    __syncthreads();
    float wvsv = wVs[h], bvsv = bVs[h];

    #define OF(JJ, CC, ORR, OII) { int sg_ = (JJ) < 16 ? 0 : 1; int jm_ = (JJ) < 16 ? (JJ) : (JJ) - 48; \
        float fr_ = f2s[((JJ) * 33 + (CC)) * 2], fi_ = f2s[((JJ) * 33 + (CC)) * 2 + 1]; \
        float wr_ = wv_s[sg_ * 512 + (jm_ * 16 + (CC)) * 2], wi_ = wv_s[sg_ * 512 + (jm_ * 16 + (CC)) * 2 + 1]; \
        ORR = fr_ * wr_ - fi_ * wi_; OII = fr_ * wi_ + fi_ * wr_; }

    for (int t = threadIdx.x; t < 2048; t += blockDim.x) {
        int jj = t >> 5, c = t & 31;
        float fr = f2s[(jj * 33 + c) * 2], fi = f2s[(jj * 33 + c) * 2 + 1];
        float vr = wvsv * fr, vi = wvsv * fi;
        if (jj == 0 && c == 0) vr += bvsv;
        if (c >= 1 && c < 16 && (jj < 16 || jj >= 48)) {
            float orr, oii; OF(jj, c, orr, oii);
            vr += orr; vi += oii;
        } else if (c == 0) {
            if (jj == 0) {
                float orr, oii; OF(0, 0, orr, oii); (void)oii;
                vr += orr;
            } else if (jj <= 15) {
                float o1r, o1i, o2r, o2i;
                OF(jj, 0, o1r, o1i); OF(64 - jj, 0, o2r, o2i);
                vr += 0.5f * (o1r + o2r); vi += 0.5f * (o1i - o2i);
            } else if (jj == 16) {
                float orr, oii; OF(48, 0, orr, oii);
                vr += 0.5f * orr; vi -= 0.5f * oii;
            } else if (jj == 48) {
                float orr, oii; OF(48, 0, orr, oii);
                vr += 0.5f * orr; vi += 0.5f * oii;
            } else if (jj >= 49) {
                float o1r, o1i, o2r, o2i;
                OF(jj, 0, o1r, o1i); OF(64 - jj, 0, o2r, o2i);
                vr += 0.5f * (o1r + o2r); vi += 0.5f * (o1i - o2i);
            }
        }
        size_t oo = ((size_t)(i * 32 + h) * 2048 + t) * 2;
        vhat[oo] = vr; vhat[oo + 1] = vi;
    }
    for (int t = threadIdx.x; t < 512; t += blockDim.x) {
        int jm = t >> 4, c = t & 15;
        int jj = jm < 16 ? jm : jm + 32;
        float orr, oii; OF(jj, c, orr, oii);
        size_t oo = ((size_t)(i * 32 + h) * 512 + t) * 2;
        svhat[oo] = orr; svhat[oo + 1] = oii;
    }
    #undef OF
}

// -------- sghat = attn x svhat
__global__ void k_ghat(const float* __restrict__ attn, const float* __restrict__ vin,
                       float* __restrict__ gout, int ncols) {
    int b = blockIdx.x, h = blockIdx.y, c0 = blockIdx.z * 256;
    __shared__ float a_sh[1024];
    __shared__ float vs[32 * 256];
    for (int t = threadIdx.x; t < 1024; t += 256)
        a_sh[t] = attn[(size_t)(b * 32 + h) * 1024 + t];
    for (int t = threadIdx.x; t < 8192; t += 256) {
        int s = t >> 8, c = t & 255;
        vs[t] = vin[(size_t)((b * 32 + s) * 32 + h) * ncols + c0 + c];
    }
    __syncthreads();
    int tq = threadIdx.x >> 5;
    int cg = threadIdx.x & 31;
    float acc[4][8];
    #pragma unroll
    for (int r = 0; r < 4; r++)
        #pragma unroll
        for (int cc = 0; cc < 8; cc++) acc[r][cc] = 0.f;
    for (int s = 0; s < 32; s++) {
        float a0 = a_sh[(tq * 4 + 0) * 32 + s];
        float a1 = a_sh[(tq * 4 + 1) * 32 + s];
        float a2 = a_sh[(tq * 4 + 2) * 32 + s];
        float a3 = a_sh[(tq * 4 + 3) * 32 + s];
        const float* vp = vs + s * 256 + cg * 8;
        #pragma unroll
        for (int cc = 0; cc < 8; cc++) {
            float v = vp[cc];
            acc[0][cc] += a0 * v; acc[1][cc] += a1 * v;
            acc[2][cc] += a2 * v; acc[3][cc] += a3 * v;
        }
    }
    #pragma unroll
    for (int r = 0; r < 4; r++)
        #pragma unroll
        for (int cc = 0; cc < 8; cc++)
            gout[(size_t)((b * 32 + tq * 4 + r) * 32 + h) * ncols + c0 + cg * 8 + cc] = acc[r][cc];
}

// -------- fused (attn x vhat) x wP -> PF partials; grid (b=2, mc=16, hg=8)
__global__ void k_gpf(const float* __restrict__ attn, const float* __restrict__ vhat,
                      const float* __restrict__ wP, float* __restrict__ PFp) {
    int b = blockIdx.x, mc = blockIdx.y, hg = blockIdx.z;
    __shared__ float a_sh[1024];
    __shared__ float vs[8192];
    int tid = threadIdx.x;
    int tq = tid >> 5, mg = tid & 31;
    float accr[4][4], acci[4][4];
    #pragma unroll
    for (int r = 0; r < 4; r++)
        #pragma unroll
        for (int m = 0; m < 4; m++) { accr[r][m] = 0.f; acci[r][m] = 0.f; }
    for (int hh = 0; hh < 4; hh++) {
        int h = hg * 4 + hh;
        __syncthreads();
        for (int t = tid; t < 1024; t += 256)
            a_sh[t] = attn[(size_t)(b * 32 + h) * 1024 + t];
        for (int t = tid; t < 8192; t += 256) {
            int s = t >> 8, c = t & 255;
            vs[t] = vhat[((size_t)((b * 32 + s) * 32 + h) * 2048 + mc * 128) * 2 + c];
        }
        __syncthreads();
        float tr[4][4], ti_[4][4];
        #pragma unroll
        for (int r = 0; r < 4; r++)
            #pragma unroll
            for (int m = 0; m < 4; m++) { tr[r][m] = 0.f; ti_[r][m] = 0.f; }
        #pragma unroll 4
        for (int s = 0; s < 32; s++) {
            float a0 = a_sh[(tq * 4 + 0) * 32 + s];
            float a1 = a_sh[(tq * 4 + 1) * 32 + s];
            float a2 = a_sh[(tq * 4 + 2) * 32 + s];
            float a3 = a_sh[(tq * 4 + 3) * 32 + s];
            const float* vp = vs + s * 256 + mg * 8;
            #pragma unroll
            for (int m = 0; m < 4; m++) {
                float vre = vp[m * 2], vim = vp[m * 2 + 1];
                tr[0][m] += a0 * vre; ti_[0][m] += a0 * vim;
                tr[1][m] += a1 * vre; ti_[1][m] += a1 * vim;
                tr[2][m] += a2 * vre; ti_[2][m] += a2 * vim;
                tr[3][m] += a3 * vre; ti_[3][m] += a3 * vim;
            }
        }
        #pragma unroll
        for (int m = 0; m < 4; m++) {
            int M = mc * 128 + mg * 4 + m;
            int jj = M >> 5, c = M & 31;
            int sgn = jj < 32 ? 0 : 1, jjm = jj & 31;
            const float* wp = wP + (((size_t)(sgn * 32 + h) * 32 + jjm) * 32 + c) * 2;
            float wr = wp[0], wi = wp[1];
            #pragma unroll
            for (int r = 0; r < 4; r++) {
                accr[r][m] += tr[r][m] * wr - ti_[r][m] * wi;
                acci[r][m] += tr[r][m] * wi + ti_[r][m] * wr;
            }
        }
    }
    #pragma unroll
    for (int r = 0; r < 4; r++) {
        int i = b * 32 + tq * 4 + r;
        #pragma unroll
        for (int m = 0; m < 4; m++) {
            int M = mc * 128 + mg * 4 + m;
            size_t o = (size_t)hg * (NI * 4096) + (size_t)i * 4096 + (size_t)M * 2;
            PFp[o] = accr[r][m]; PFp[o + 1] = acci[r][m];
        }
    }
}

// -------- window extras into PF partial slot 0
__global__ void k_pfw(const float* __restrict__ sghat, const float* __restrict__ wPs,
                      float* __restrict__ PFp) {
    int i = blockIdx.x;
    int w = blockIdx.y * 256 + threadIdx.x;
    __shared__ float wps_[32];
    if (threadIdx.x < 32) wps_[threadIdx.x] = wPs[threadIdx.x];
    __syncthreads();
    int jm = w >> 4, c = w & 15;
    int jj = jm < 16 ? jm : jm + 32;
    int t = jj * 32 + c;
    float re = 0.f, im = 0.f;
    #pragma unroll 4
    for (int h = 0; h < 32; h++) {
        const float* sg = sghat + ((size_t)(i * 32 + h) * 512 + w) * 2;
        re += wps_[h] * sg[0]; im += wps_[h] * sg[1];
    }
    size_t o = (size_t)i * 4096 + (size_t)t * 2;
    PFp[o] += re; PFp[o + 1] += im;
}

// -------- token mix y2
__global__ void k_tokmix(const float* __restrict__ attn, const float* __restrict__ xan,
                         const float* __restrict__ wPs, const float* __restrict__ wVs,
                         const float* __restrict__ bVs, const float* __restrict__ bPs,
                         float* __restrict__ y2) {
    int b = blockIdx.x;
    int pbase = blockIdx.y * 256;
    int tid = threadIdx.x;
    __shared__ float C[1024];
    __shared__ float xs[32 * 256];
    __shared__ float cb_s;
    {
        int t = tid >> 3, s0 = (tid & 7) * 4;
        float c0 = 0.f, c1 = 0.f, c2 = 0.f, c3 = 0.f;
        for (int h = 0; h < 32; h++) {
            float w = wPs[h] * wVs[h];
            const float* ap = attn + (size_t)(b * 32 + h) * 1024 + t * 32 + s0;
            c0 += w * ap[0]; c1 += w * ap[1]; c2 += w * ap[2]; c3 += w * ap[3];
        }
        C[t * 32 + s0] = c0; C[t * 32 + s0 + 1] = c1;
        C[t * 32 + s0 + 2] = c2; C[t * 32 + s0 + 3] = c3;
    }
    if (tid == 0) {
        float cb = bPs[0];
        for (int h = 0; h < 32; h++) cb += wPs[h] * bVs[h];
        cb_s = cb;
    }
    for (int t = tid; t < 8192; t += 256) {
        int s = t >> 8, c = t & 255;
        xs[t] = xan[(size_t)(b * 32 + s) * HW + pbase + c];
    }
    __syncthreads();
    int t = tid >> 3, pg = tid & 7;
    float acc[32];
    #pragma unroll
    for (int pp = 0; pp < 32; pp++) acc[pp] = 0.f;
    for (int s = 0; s < 32; s++) {
        float cc = C[t * 32 + s];
        const float* xp = xs + s * 256 + pg * 32;
        #pragma unroll
        for (int pp = 0; pp < 32; pp++) acc[pp] += cc * xp[pp];
    }
    float cb = cb_s;
    #pragma unroll
    for (int pp = 0; pp < 32; pp++)
        y2[(size_t)(b * 32 + t) * HW + pbase + pg * 32 + pp] = acc[pp] + cb;
}

extern "C" void kernel_launch(void* const* d_in, const int* in_sizes, int n_in,
                              void* d_out, int out_size) {
    const float* x    = (const float*)d_in[0];
    const float* wK   = (const float*)d_in[1];
    const float* wKs  = (const float*)d_in[2];
    const float* bKs  = (const float*)d_in[3];
    const float* wQ   = (const float*)d_in[4];
    const float* wQs  = (const float*)d_in[5];
    const float* bQs  = (const float*)d_in[6];
    const float* wV   = (const float*)d_in[7];
    const float* wVs  = (const float*)d_in[8];
    const float* bVs  = (const float*)d_in[9];
    const float* wP   = (const float*)d_in[10];
    const float* wPs  = (const float*)d_in[11];
    const float* bPs  = (const float*)d_in[12];
    const float* wM0  = (const float*)d_in[13];
    const float* wM0s = (const float*)d_in[14];
    const float* bM0s = (const float*)d_in[15];
    const float* wM1  = (const float*)d_in[16];
    const float* wM1s = (const float*)d_in[17];
    const float* bM1s = (const float*)d_in[18];
    const float* ng   = (const float*)d_in[19];
    const float* nb   = (const float*)d_in[20];
    float* out = (float*)d_out;

    float *p_xan, *p_F1, *p_F2, *p_R64, *p_k, *p_q, *p_scp, *p_attn;
    float *p_vhat, *p_svhat, *p_sghat, *p_PFp, *p_y2;
    float *p_fno, *p_att, *p_an, *p_m, *p_MF1, *p_MF2;
    cudaGetSymbolAddress((void**)&p_xan,   s_xan);
    cudaGetSymbolAddress((void**)&p_F1,    s_F1);
    cudaGetSymbolAddress((void**)&p_F2,    s_F2);
    cudaGetSymbolAddress((void**)&p_R64,   s_R64);
    cudaGetSymbolAddress((void**)&p_k,     s_k);
    cudaGetSymbolAddress((void**)&p_q,     s_q);
    cudaGetSymbolAddress((void**)&p_scp,   s_scp);
    cudaGetSymbolAddress((void**)&p_attn,  s_attn);
    cudaGetSymbolAddress((void**)&p_vhat,  s_vhat);
    cudaGetSymbolAddress((void**)&p_svhat, s_svhat);
    cudaGetSymbolAddress((void**)&p_sghat, s_sghat);
    cudaGetSymbolAddress((void**)&p_PFp,   s_PFp);
    cudaGetSymbolAddress((void**)&p_y2,    s_y2);
    cudaGetSymbolAddress((void**)&p_fno,   s_fno);
    cudaGetSymbolAddress((void**)&p_att,   s_att);
    cudaGetSymbolAddress((void**)&p_an,    s_an);
    cudaGetSymbolAddress((void**)&p_m,     s_m);
    cudaGetSymbolAddress((void**)&p_MF1,   s_MF1);
    cudaGetSymbolAddress((void**)&p_MF2,   s_MF2);

    const size_t PSTRIDE = (size_t)NI * 4096;

    k_init<<<1, 128>>>();

    // xa_n (idx0) + partial spectrum
    k_inorm<<<NI, 512>>>(x, nullptr, p_xan, ng, nb, 0, nullptr);
    k_fwd1<33><<<dim3(NI, 4), 264>>>(p_xan, p_F1);
    k_fwd2<<<dim3(NI, 4), 576>>>(p_F1, p_F2, 33);

    // resampled xa_n 64x64
    k_inv2<<<dim3(NI, 2), 512>>>(p_F2, nullptr, p_R64, 33, 64, nullptr, 1, 0);

    // K + Q fused
    k_kq<<<dim3(NI, NH, 2), 256>>>(p_F2, wK, wQ, p_R64, wKs, bKs, wQs, bQs, p_k, p_q);

    // attention weights (split-d partials + softmax)
    k_scores_part<<<dim3(64, 8), 256>>>(p_q, p_k, p_scp);
    k_softmax<<<64, 1024>>>(p_scp, p_attn);

    // mode-space V / attention / projection
    k_vhat<<<dim3(NI, NH), 256>>>(p_F2, wV, wVs, bVs, p_vhat, p_svhat);
    k_ghat<<<dim3(2, 32, 4), 256>>>(p_attn, p_svhat, p_sghat, 1024);
    k_gpf<<<dim3(2, 16, 8), 256>>>(p_attn, p_vhat, wP, p_PFp);
    k_pfw<<<dim3(NI, 2), 256>>>(p_sghat, wPs, p_PFp);
    k_tokmix<<<dim3(2, 64), 256>>>(p_attn, p_xan, wPs, wVs, bVs, bPs, p_y2);
    k_inv2<<<dim3(NI, 4), 512>>>(p_PFp, nullptr, p_fno, 32, 128, p_y2, 8, PSTRIDE);

    // att = IN1(projd + xa); an = IN2(att)
    k_norm12<<<NI, 512>>>(p_fno, x, p_att, p_an, ng, nb);

    // mixer layer 0 (idx3 + gelu)
    k_fwd1<32><<<dim3(NI, 4), 256>>>(p_an, p_MF1);
    k_fwd2<<<dim3(NI, 4), 512>>>(p_MF1, p_MF2, 32);
    k_inv2<<<dim3(NI, 4), 512>>>(p_MF2, wM0, p_fno, 32, 128, nullptr, 1, 0);
    k_normeps<<<NI, 512>>>(p_fno, p_an, p_m, ng, nb, 3, wM0s, bM0s, 1);

    // mixer layer 1 (idx4)
    k_fwd1<32><<<dim3(NI, 4), 256>>>(p_m, p_MF1);
    k_fwd2<<<dim3(NI, 4), 512>>>(p_MF1, p_MF2, 32);
    k_inv2<<<dim3(NI, 4), 512>>>(p_MF2, wM1, p_fno, 32, 128, nullptr, 1, 0);
    k_normeps<<<NI, 512>>>(p_fno, p_m, p_m, ng, nb, 4, wM1s, bM1s, 0);

    // output = IN5(m) + att
    k_inorm<<<NI, 512>>>(p_m, nullptr, out, ng, nb, 5, p_att);
}

// round 14
// speedup vs baseline: 1.9026x; 1.2419x over previous
#include <cuda_runtime.h>
#include <cuda_bf16.h>
#include <cstdint>
#include <cstddef>

#define NI 64
#define NH 32
#define HW 16384

__device__ float d_c[128];
__device__ float d_s[128];

__device__ float s_xan [NI*HW];
__device__ float s_F1  [NI*128*33*2];
__device__ float s_F2  [NI*64*33*2];
__device__ float s_u   [(size_t)NI*NH*1152];
__device__ float s_v   [(size_t)NI*NH*1152];
__device__ float s_rcq [NI*3200];
__device__ float s_rck [NI*3200];
__device__ float s_scpA[3*64*1024];
__device__ float s_scp0[5*2*1024];
__device__ float s_attn[64*1024];
__device__ float s_vhat [(size_t)NI*NH*4096];
__device__ float s_svhat[(size_t)NI*NH*1024];
__device__ float s_sghat[(size_t)NI*NH*1024];
__device__ float s_PFp [(size_t)8*NI*4096];
__device__ float s_y2  [NI*HW];
__device__ float s_fno [NI*HW];
__device__ float s_att [NI*HW];
__device__ float s_an  [NI*HW];
__device__ float s_m   [NI*HW];
__device__ float s_MF1 [NI*128*32*2];
__device__ float s_MF2 [NI*64*32*2];

__device__ __forceinline__ void load_tables(float* cs, float* ss) {
    for (int t = threadIdx.x; t < 128; t += blockDim.x) { cs[t] = d_c[t]; ss[t] = d_s[t]; }
}

__global__ void k_init() {
    int k = threadIdx.x;
    d_c[k] = cospif(k / 64.0f);
    d_s[k] = sinpif(k / 64.0f);
}

// block stats via warp shuffles; 512 threads
__device__ __forceinline__ void block_stats(float sum, float sq, float* shm,
                                            float& mean, float& istd) {
    #pragma unroll
    for (int o = 16; o; o >>= 1) {
        sum += __shfl_xor_sync(0xffffffffu, sum, o);
        sq  += __shfl_xor_sync(0xffffffffu, sq, o);
    }
    int wid = threadIdx.x >> 5;
    if ((threadIdx.x & 31) == 0) { shm[wid] = sum; shm[16 + wid] = sq; }
    __syncthreads();
    if (threadIdx.x < 32) {
        float a = (threadIdx.x < 16) ? shm[threadIdx.x] : 0.f;
        float b = (threadIdx.x < 16) ? shm[16 + threadIdx.x] : 0.f;
        #pragma unroll
        for (int o = 8; o; o >>= 1) {
            a += __shfl_xor_sync(0xffffffffu, a, o);
            b += __shfl_xor_sync(0xffffffffu, b, o);
        }
        if (threadIdx.x == 0) {
            float m = a * (1.f / HW);
            float var = b * (1.f / HW) - m * m;
            shm[32] = m; shm[33] = rsqrtf(var + 1e-5f);
        }
    }
    __syncthreads();
    mean = shm[32]; istd = shm[33];
}

// -------- instance norm (512 thr, float4); optional pre-add & post-add
__global__ void k_inorm(const float* __restrict__ src, const float* __restrict__ add,
                        float* __restrict__ dst, const float* __restrict__ gA,
                        const float* __restrict__ bA, int gi, const float* __restrict__ post) {
    int img = blockIdx.x, tid = threadIdx.x;
    const float4* s4 = (const float4*)(src + (size_t)img * HW);
    const float4* a4 = add ? (const float4*)(add + (size_t)img * HW) : nullptr;
    const float4* p4 = post ? (const float4*)(post + (size_t)img * HW) : nullptr;
    float4* d4 = (float4*)(dst + (size_t)img * HW);
    float sum = 0.f, sq = 0.f;
    for (int p = tid; p < 4096; p += 512) {
        float4 v = s4[p];
        if (a4) { float4 a = a4[p]; v.x += a.x; v.y += a.y; v.z += a.z; v.w += a.w; }
        sum += v.x + v.y + v.z + v.w;
        sq += v.x * v.x + v.y * v.y + v.z * v.z + v.w * v.w;
    }
    __shared__ float shm[34];
    float m, is;
    block_stats(sum, sq, shm, m, is);
    float g = gA[gi], bb = bA[gi];
    for (int p = tid; p < 4096; p += 512) {
        float4 v = s4[p];
        if (a4) { float4 a = a4[p]; v.x += a.x; v.y += a.y; v.z += a.z; v.w += a.w; }
        float4 r;
        r.x = (v.x - m) * is * g + bb; r.y = (v.y - m) * is * g + bb;
        r.z = (v.z - m) * is * g + bb; r.w = (v.w - m) * is * g + bb;
        if (p4) { float4 q = p4[p]; r.x += q.x; r.y += q.y; r.z += q.z; r.w += q.w; }
        d4[p] = r;
    }
}

// -------- fused IN1(fno+x) -> att, IN2(att) -> an
__global__ void k_norm12(const float* __restrict__ fno, const float* __restrict__ x,
                         float* __restrict__ att, float* __restrict__ an,
                         const float* __restrict__ gA, const float* __restrict__ bA) {
    int img = blockIdx.x, tid = threadIdx.x;
    const float4* f4 = (const float4*)(fno + (size_t)img * HW);
    const float4* x4 = (const float4*)(x + (size_t)img * HW);
    float4* att4 = (float4*)(att + (size_t)img * HW);
    float4* an4  = (float4*)(an + (size_t)img * HW);
    float sum = 0.f, sq = 0.f;
    for (int p = tid; p < 4096; p += 512) {
        float4 v = f4[p], a = x4[p];
        v.x += a.x; v.y += a.y; v.z += a.z; v.w += a.w;
        sum += v.x + v.y + v.z + v.w;
        sq += v.x * v.x + v.y * v.y + v.z * v.z + v.w * v.w;
    }
    __shared__ float shm[34];
    float m, is1;
    block_stats(sum, sq, shm, m, is1);
    __shared__ float is2_s;
    if (tid == 0) {
        float g1 = gA[1];
        float var = 1.f / (is1 * is1) - 1e-5f;
        float varatt = g1 * g1 * var * is1 * is1;
        is2_s = rsqrtf(varatt + 1e-5f);
    }
    __syncthreads();
    float g1 = gA[1], b1 = bA[1], g2 = gA[2], b2 = bA[2], is2 = is2_s;
    for (int p = tid; p < 4096; p += 512) {
        float4 v = f4[p], a = x4[p];
        v.x += a.x; v.y += a.y; v.z += a.z; v.w += a.w;
        float4 r, n;
        r.x = (v.x - m) * is1 * g1 + b1; r.y = (v.y - m) * is1 * g1 + b1;
        r.z = (v.z - m) * is1 * g1 + b1; r.w = (v.w - m) * is1 * g1 + b1;
        n.x = (r.x - b1) * is2 * g2 + b2; n.y = (r.y - b1) * is2 * g2 + b2;
        n.z = (r.z - b1) * is2 * g2 + b2; n.w = (r.w - b1) * is2 * g2 + b2;
        att4[p] = r; an4[p] = n;
    }
}

__device__ __forceinline__ float gelu1(float v) {
    return 0.5f * v * (1.f + erff(v * 0.70710678118654752f));
}

// -------- fused IN(gi)(src) then dst = [gelu](norm + ws*src2 + bs)
__global__ void k_normeps(const float* __restrict__ src, const float* __restrict__ src2,
                          float* __restrict__ dst, const float* __restrict__ gA,
                          const float* __restrict__ bA, int gi,
                          const float* __restrict__ ws, const float* __restrict__ bs,
                          int dogelu) {
    int img = blockIdx.x, tid = threadIdx.x;
    const float4* s4 = (const float4*)(src + (size_t)img * HW);
    const float4* s24 = (const float4*)(src2 + (size_t)img * HW);
    float4* d4 = (float4*)(dst + (size_t)img * HW);
    float sum = 0.f, sq = 0.f;
    for (int p = tid; p < 4096; p += 512) {
        float4 v = s4[p];
        sum += v.x + v.y + v.z + v.w;
        sq += v.x * v.x + v.y * v.y + v.z * v.z + v.w * v.w;
    }
    __shared__ float shm[34];
    float m, is;
    block_stats(sum, sq, shm, m, is);
    float g = gA[gi], bb = bA[gi], wsv = ws[0], bsv = bs[0];
    for (int p = tid; p < 4096; p += 512) {
        float4 v = s4[p], a = s24[p], r;
        r.x = (v.x - m) * is * g + bb + wsv * a.x + bsv;
        r.y = (v.y - m) * is * g + bb + wsv * a.y + bsv;
        r.z = (v.z - m) * is * g + bb + wsv * a.z + bsv;
        r.w = (v.w - m) * is * g + bb + wsv * a.w + bsv;
        if (dogelu) { r.x = gelu1(r.x); r.y = gelu1(r.y); r.z = gelu1(r.z); r.w = gelu1(r.w); }
        d4[p] = r;
    }
}

// -------- fwd stage1 (cols); 4-row batching, twiddle recurrence
template <int NC>
__global__ void k_fwd1(const float* __restrict__ x, float* __restrict__ out) {
    int n = blockIdx.x, hb = blockIdx.y;
    __shared__ float xs[32 * 128];
    __shared__ float cs[128], ss[128];
    load_tables(cs, ss);
    for (int t = threadIdx.x; t < 32 * 128; t += blockDim.x)
        xs[t] = x[((size_t)n * 128 + hb * 32) * 128 + t];
    __syncthreads();
    int t = threadIdx.x;
    if (t >= 8 * NC) return;
    int hg = t / NC, c = t % NC;
    float rr[4] = {0, 0, 0, 0}, ii[4] = {0, 0, 0, 0};
    float wr = 1.f, wi = 0.f;
    float str = cs[c], sti = -ss[c];
    #pragma unroll 4
    for (int w = 0; w < 128; w++) {
        #pragma unroll
        for (int kk = 0; kk < 4; kk++) {
            float v = xs[(hg * 4 + kk) * 128 + w];
            rr[kk] += v * wr; ii[kk] += v * wi;
        }
        float nwr = wr * str - wi * sti;
        wi = wr * sti + wi * str;
        wr = nwr;
    }
    #pragma unroll
    for (int kk = 0; kk < 4; kk++) {
        int row = hb * 32 + hg * 4 + kk;
        size_t o = ((size_t)(n * 128 + row) * NC + c) * 2;
        out[o] = rr[kk] * (1.f / 128.f); out[o + 1] = ii[kk] * (1.f / 128.f);
    }
}

// -------- fwd stage2 (rows); c-chunked, twiddle recurrence
__global__ void k_fwd2(const float* __restrict__ F1, float* __restrict__ F2o, int NC) {
    int n = blockIdx.x;
    int chunk = (NC + gridDim.y - 1) / gridDim.y;
    int c0 = blockIdx.y * chunk;
    int cn = NC - c0 < chunk ? NC - c0 : chunk;
    __shared__ float fs[128 * 9 * 2];
    __shared__ float cs[128], ss[128];
    load_tables(cs, ss);
    for (int t = threadIdx.x; t < 128 * cn * 2; t += blockDim.x) {
        int h = t / (cn * 2), rem = t % (cn * 2);
        fs[t] = F1[((size_t)(n * 128 + h) * NC + c0) * 2 + rem];
    }
    __syncthreads();
    int tid = threadIdx.x;
    if (tid >= 64 * cn) return;
    int jr = tid / cn, cl = tid % cn;
    int r = jr < 32 ? jr : jr + 64;
    float wr = 1.f, wi = 0.f;
    float str = cs[r & 127], sti = -ss[r & 127];
    float re = 0.f, im = 0.f;
    #pragma unroll 4
    for (int h = 0; h < 128; h++) {
        float ar = fs[(h * cn + cl) * 2], ai = fs[(h * cn + cl) * 2 + 1];
        re += ar * wr - ai * wi;
        im += ar * wi + ai * wr;
        float nwr = wr * str - wi * sti;
        wi = wr * sti + wi * str;
        wr = nwr;
    }
    size_t oo = ((size_t)(n * 64 + jr) * NC + c0 + cl) * 2;
    F2o[oo] = re * (1.f / 128.f); F2o[oo + 1] = im * (1.f / 128.f);
}

// -------- fused inverse (row+col), optional weight mult, partial sums, pixel add
__global__ void k_inv2(const float* __restrict__ src, const float* __restrict__ wmul,
                       float* __restrict__ dst, int NC, int P, const float* __restrict__ yadd,
                       int nparts, size_t pstride) {
    int n = blockIdx.x;
    int ybase = blockIdx.y * 32;
    __shared__ float fs[64 * 33 * 2];
    __shared__ float rr[32 * 33 * 2];
    __shared__ float cs[128], ss[128];
    load_tables(cs, ss);
    for (int t = threadIdx.x; t < 64 * NC; t += blockDim.x) {
        int jj = t / NC, c = t % NC;
        size_t base = ((size_t)n * 64 * NC + t) * 2;
        float ar = 0.f, ai = 0.f;
        for (int p = 0; p < nparts; p++) {
            ar += src[p * pstride + base];
            ai += src[p * pstride + base + 1];
        }
        if (wmul) {
            int sgn = jj < 32 ? 0 : 1, jjm = jj & 31;
            const float* wp = wmul + (((size_t)sgn * 32 + jjm) * 32 + c) * 2;
            float wr = wp[0], wi = wp[1];
            float r2 = ar * wr - ai * wi, i2 = ar * wi + ai * wr;
            ar = r2; ai = i2;
        }
        fs[t * 2] = ar; fs[t * 2 + 1] = ai;
    }
    __syncthreads();
    int step = 128 / P;
    int CG = (NC + 3) >> 2;
    for (int t = threadIdx.x; t < 32 * CG; t += blockDim.x) {
        int yl = t / CG, cg = t % CG;
        int y = ybase + yl, c0 = cg * 4;
        float accr[4] = {0, 0, 0, 0}, acci[4] = {0, 0, 0, 0};
        int ys = (y * step) & 127;
        float stwr = cs[ys], stwi = ss[ys];
        float wr = 1.f, wi = 0.f;
        #pragma unroll 4
        for (int jr = 0; jr < 64; jr++) {
            if (jr == 32) {
                int a = ((P - 32) * y * step) & 127;
                wr = cs[a]; wi = ss[a];
            }
            #pragma unroll
            for (int cc = 0; cc < 4; cc++) {
                if (c0 + cc < NC) {
                    float ar = fs[(jr * NC + c0 + cc) * 2], ai = fs[(jr * NC + c0 + cc) * 2 + 1];
                    accr[cc] += ar * wr - ai * wi;
                    acci[cc] += ar * wi + ai * wr;
                }
            }
            float nwr = wr * stwr - wi * stwi;
            wi = wr * stwi + wi * stwr;
            wr = nwr;
        }
        #pragma unroll
        for (int cc = 0; cc < 4; cc++) {
            if (c0 + cc < NC) {
                rr[(yl * NC + c0 + cc) * 2] = accr[cc];
                rr[(yl * NC + c0 + cc) * 2 + 1] = acci[cc];
            }
        }
    }
    __syncthreads();
    int nyq = ((NC - 1) * 2 == P) ? 1 : 0;
    int cmax = nyq ? NC - 1 : NC;
    int PP = P * P;
    int slots = 8 * P;
    for (int t = threadIdx.x; t < slots; t += blockDim.x) {
        int x = t % P, yg = t / P;
        int yl0 = yg * 4;
        float acc[4];
        #pragma unroll
        for (int yy = 0; yy < 4; yy++) acc[yy] = rr[((yl0 + yy) * NC) * 2];
        int xs_ = (x * step) & 127;
        float stwr = cs[xs_], stwi = ss[xs_];
        float wr = stwr, wi = stwi;
        #pragma unroll 4
        for (int c = 1; c < cmax; c++) {
            #pragma unroll
            for (int yy = 0; yy < 4; yy++) {
                float re = rr[((yl0 + yy) * NC + c) * 2], im = rr[((yl0 + yy) * NC + c) * 2 + 1];
                acc[yy] += 2.f * (re * wr - im * wi);
            }
            float nwr = wr * stwr - wi * stwi;
            wi = wr * stwi + wi * stwr;
            wr = nwr;
        }
        if (nyq) {
            #pragma unroll
            for (int yy = 0; yy < 4; yy++)
                acc[yy] += rr[((yl0 + yy) * NC + NC - 1) * 2] * wr;
        }
        #pragma unroll
        for (int yy = 0; yy < 4; yy++) {
            int p = (ybase + yl0 + yy) * P + x;
            float v = acc[yy];
            if (yadd) v += yadd[(size_t)n * PP + p];
            dst[(size_t)n * PP + p] = v;
        }
    }
}

// -------- Rhat complement pack (1599 modes + 1 pad): qC = Rhat|_C, kC = wc*Rhat|_C
__global__ void k_rhat(const float* __restrict__ F2, float* __restrict__ qC,
                       float* __restrict__ kC) {
    int i = blockIdx.x;
    __shared__ float f2s[4224];
    for (int t = threadIdx.x; t < 4224; t += blockDim.x)
        f2s[t] = F2[(size_t)i * 4224 + t];
    __syncthreads();
    for (int idx = threadIdx.x; idx < 1600; idx += blockDim.x) {
        float rr = 0.f, ri = 0.f, wc = 2.f;
        if (idx < 1599) {
            int y, c;
            if (idx < 31)        { c = 0;  y = 17 + idx;                 wc = 1.f; }
            else if (idx < 511)  { int q = idx - 31;  c = 1 + q / 32;  y = 16 + q % 32; }
            else if (idx < 1535) { int q = idx - 511; c = 16 + q / 64; y = q % 64; }
            else                 { c = 32; y = idx - 1535;               wc = 1.f; }
            if (c == 0 || c == 32) {
                int ym = (64 - y) & 63;
                rr = 0.5f * (f2s[(y * 33 + c) * 2]     + f2s[(ym * 33 + c) * 2]);
                ri = 0.5f * (f2s[(y * 33 + c) * 2 + 1] - f2s[(ym * 33 + c) * 2 + 1]);
            } else {
                rr = f2s[(y * 33 + c) * 2]; ri = f2s[(y * 33 + c) * 2 + 1];
            }
        }
        size_t o = (size_t)i * 3200 + idx * 2;
        qC[o] = rr; qC[o + 1] = ri;
        kC[o] = wc * rr; kC[o + 1] = wc * ri;
    }
}

// -------- build u,v over support S (513 modes, padded to 576 complex = 1152 floats)
__global__ void k_uv(const float* __restrict__ F2,
                     const float* __restrict__ wQ, const float* __restrict__ wQs,
                     const float* __restrict__ bQs,
                     const float* __restrict__ wK, const float* __restrict__ wKs,
                     const float* __restrict__ bKs,
                     float* __restrict__ u, float* __restrict__ v) {
    int i = blockIdx.x, hg = blockIdx.y;
    __shared__ float f2s[4224];
    for (int t = threadIdx.x; t < 4224; t += blockDim.x)
        f2s[t] = F2[(size_t)i * 4224 + t];
    __syncthreads();
    for (int hh = 0; hh < 8; hh++) {
        int h = hg * 8 + hh;
        float wqs = wQs[h], wks = wKs[h], bq = bQs[h], bk = bKs[h];
        for (int ms = threadIdx.x; ms < 576; ms += blockDim.x) {
            float ur = 0.f, ui = 0.f, vr = 0.f, vi = 0.f;
            if (ms < 513) {
                int y, c; float wc;
                if (ms < 33) { c = 0; y = ms <= 16 ? ms : ms + 31; wc = 1.f; }
                else { int q = ms - 33; c = 1 + q / 32; int yy = q % 32;
                       y = yy < 16 ? yy : yy + 32; wc = 2.f; }
                // Rhat (sym only needed for c==0 here)
                float rr, ri;
                if (c == 0) {
                    int ym = (64 - y) & 63;
                    rr = 0.5f * (f2s[(y * 33) * 2]     + f2s[(ym * 33) * 2]);
                    ri = 0.5f * (f2s[(y * 33) * 2 + 1] - f2s[(ym * 33) * 2 + 1]);
                } else {
                    rr = f2s[(y * 33 + c) * 2]; ri = f2s[(y * 33 + c) * 2 + 1];
                }
                // spectral-conv effective modes
                float aqr, aqi, akr, aki;
                if (c > 0) {
                    int sgn = y < 16 ? 0 : 1, jm = y < 16 ? y : y - 48;
                    const float* wq_ = wQ + (((size_t)(sgn * 32 + h) * 16 + jm) * 16 + c) * 2;
                    const float* wk_ = wK + (((size_t)(sgn * 32 + h) * 16 + jm) * 16 + c) * 2;
                    float fr = f2s[(y * 33 + c) * 2], fi = f2s[(y * 33 + c) * 2 + 1];
                    aqr = fr * wq_[0] - fi * wq_[1]; aqi = fr * wq_[1] + fi * wq_[0];
                    akr = fr * wk_[0] - fi * wk_[1]; aki = fr * wk_[1] + fi * wk_[0];
                } else {
                    int ym = (64 - y) & 63;
                    float a1r, a1i, a2r, a2i;
                    #define EVA(YY, W, OR_, OI_) { \
                        if ((YY) < 16 || (YY) >= 48) { \
                            int sg_ = (YY) < 16 ? 0 : 1, jm_ = (YY) < 16 ? (YY) : (YY) - 48; \
                            const float* wp_ = W + (((size_t)(sg_ * 32 + h) * 16 + jm_) * 16) * 2; \
                            float fr_ = f2s[((YY) * 33) * 2], fi_ = f2s[((YY) * 33) * 2 + 1]; \
                            OR_ = fr_ * wp_[0] - fi_ * wp_[1]; OI_ = fr_ * wp_[1] + fi_ * wp_[0]; \
                        } else { OR_ = 0.f; OI_ = 0.f; } }
                    EVA(y, wQ, a1r, a1i); EVA(ym, wQ, a2r, a2i);
                    aqr = 0.5f * (a1r + a2r); aqi = 0.5f * (a1i - a2i);
                    EVA(y, wK, a1r, a1i); EVA(ym, wK, a2r, a2i);
                    akr = 0.5f * (a1r + a2r); aki = 0.5f * (a1i - a2i);
                    #undef EVA
                }
                ur = aqr + wqs * rr + (ms == 0 ? bq : 0.f);
                ui = aqi + wqs * ri;
                vr = wc * (akr + wks * rr + (ms == 0 ? bk : 0.f));
                vi = wc * (aki + wks * ri);
            }
            size_t o = ((size_t)(i * 32 + h) * 1152 + ms * 2);
            u[o] = ur; u[o + 1] = ui;
            v[o] = vr; v[o + 1] = vi;
        }
    }
}

// -------- generic Gram partials: out[t,s] = dot(q_row(t), k_row(s)); d chunked over gridDim.y
__global__ void k_gemm_part(const float* __restrict__ q, const float* __restrict__ k,
                            float* __restrict__ scp, int dfl, int hs) {
    int G = gridDim.x;
    int bh = blockIdx.x;
    int b = bh / hs, h = bh - b * hs;
    int ch = blockIdx.y;
    int chunk = dfl / gridDim.y;
    int tid = threadIdx.x;
    int ti = tid >> 4, si = tid & 15;
    __shared__ float qs_[32 * 132], ks_[32 * 132];
    float a00 = 0.f, a01 = 0.f, a10 = 0.f, a11 = 0.f;
    for (int kk = ch * chunk; kk < ch * chunk + chunk; kk += 128) {
        __syncthreads();
        for (int t = tid; t < 4096; t += 256) {
            int row = t >> 7, col = t & 127;
            size_t base = ((size_t)(b * 32 + row) * hs + h) * dfl + kk + col;
            qs_[row * 132 + col] = q[base];
            ks_[row * 132 + col] = k[base];
        }
        __syncthreads();
        #pragma unroll 4
        for (int j = 0; j < 128; j++) {
            float q0 = qs_[(2 * ti) * 132 + j], q1 = qs_[(2 * ti + 1) * 132 + j];
            float k0 = ks_[(2 * si) * 132 + j], k1 = ks_[(2 * si + 1) * 132 + j];
            a00 += q0 * k0; a01 += q0 * k1; a10 += q1 * k0; a11 += q1 * k1;
        }
    }
    float* sp = scp + ((size_t)(ch * G + bh)) * 1024;
    sp[(2 * ti) * 32 + 2 * si]         = a00;
    sp[(2 * ti) * 32 + 2 * si + 1]     = a01;
    sp[(2 * ti + 1) * 32 + 2 * si]     = a10;
    sp[(2 * ti + 1) * 32 + 2 * si + 1] = a11;
}

// -------- combine: score = 64*(sum scpA + wQs[h]*wKs[h]*sum scp0) ; softmax per row
__global__ void k_softmax(const float* __restrict__ scpA, const float* __restrict__ scp0,
                          const float* __restrict__ wQs, const float* __restrict__ wKs,
                          float* __restrict__ attn) {
    int bh = blockIdx.x, tid = threadIdx.x;
    int b = bh >> 5, h = bh & 31;
    float v = 0.f;
    #pragma unroll
    for (int c = 0; c < 3; c++) v += scpA[((size_t)c * 64 + bh) * 1024 + tid];
    float g = 0.f;
    #pragma unroll
    for (int c = 0; c < 5; c++) g += scp0[((size_t)c * 2 + b) * 1024 + tid];
    v = (v + wQs[h] * wKs[h] * g) * 64.f;
    float mx = v;
    for (int o = 16; o > 0; o >>= 1) mx = fmaxf(mx, __shfl_xor_sync(0xffffffffu, mx, o));
    float e = expf(v - mx), sm = e;
    for (int o = 16; o > 0; o >>= 1) sm += __shfl_xor_sync(0xffffffffu, sm, o);
    attn[(size_t)bh * 1024 + tid] = e / sm;
}

// -------- Vhat + SpecVhat
__global__ void k_vhat(const float* __restrict__ F2, const float* __restrict__ wV,
                       const float* __restrict__ wVs, const float* __restrict__ bVs,
                       float* __restrict__ vhat, float* __restrict__ svhat) {
    int i = blockIdx.x, h = blockIdx.y;
    __shared__ float f2s[64 * 33 * 2];
    __shared__ float wv_s[1024];
    for (int t = threadIdx.x; t < 64 * 33 * 2; t += blockDim.x)
        f2s[t] = F2[(size_t)i * (64 * 33 * 2) + t];
    for (int t = threadIdx.x; t < 1024; t += blockDim.x) {
        int sgn = t >> 9;
        wv_s[t] = wV[((size_t)(sgn * 32 + h) * 256) * 2 + (t & 511)];
    }
    __syncthreads();
    float wvsv = wVs[h], bvsv = bVs[h];

    #define OF(JJ, CC, ORR, OII) { int sg_ = (JJ) < 16 ? 0 : 1; int jm_ = (JJ) < 16 ? (JJ) : (JJ) - 48; \
        float fr_ = f2s[((JJ) * 33 + (CC)) * 2], fi_ = f2s[((JJ) * 33 + (CC)) * 2 + 1]; \
        float wr_ = wv_s[sg_ * 512 + (jm_ * 16 + (CC)) * 2], wi_ = wv_s[sg_ * 512 + (jm_ * 16 + (CC)) * 2 + 1]; \
        ORR = fr_ * wr_ - fi_ * wi_; OII = fr_ * wi_ + fi_ * wr_; }

    for (int t = threadIdx.x; t < 2048; t += blockDim.x) {
        int jj = t >> 5, c = t & 31;
        float fr = f2s[(jj * 33 + c) * 2], fi = f2s[(jj * 33 + c) * 2 + 1];
        float vr = wvsv * fr, vi = wvsv * fi;
        if (jj == 0 && c == 0) vr += bvsv;
        if (c >= 1 && c < 16 && (jj < 16 || jj >= 48)) {
            float orr, oii; OF(jj, c, orr, oii);
            vr += orr; vi += oii;
        } else if (c == 0) {
            if (jj == 0) {
                float orr, oii; OF(0, 0, orr, oii); (void)oii;
                vr += orr;
            } else if (jj <= 15) {
                float o1r, o1i, o2r, o2i;
                OF(jj, 0, o1r, o1i); OF(64 - jj, 0, o2r, o2i);
                vr += 0.5f * (o1r + o2r); vi += 0.5f * (o1i - o2i);
            } else if (jj == 16) {
                float orr, oii; OF(48, 0, orr, oii);
                vr += 0.5f * orr; vi -= 0.5f * oii;
            } else if (jj == 48) {
                float orr, oii; OF(48, 0, orr, oii);
                vr += 0.5f * orr; vi += 0.5f * oii;
            } else if (jj >= 49) {
                float o1r, o1i, o2r, o2i;
                OF(jj, 0, o1r, o1i); OF(64 - jj, 0, o2r, o2i);
                vr += 0.5f * (o1r + o2r); vi += 0.5f * (o1i - o2i);
            }
        }
        size_t oo = ((size_t)(i * 32 + h) * 2048 + t) * 2;
        vhat[oo] = vr; vhat[oo + 1] = vi;
    }
    for (int t = threadIdx.x; t < 512; t += blockDim.x) {
        int jm = t >> 4, c = t & 15;
        int jj = jm < 16 ? jm : jm + 32;
        float orr, oii; OF(jj, c, orr, oii);
        size_t oo = ((size_t)(i * 32 + h) * 512 + t) * 2;
        svhat[oo] = orr; svhat[oo + 1] = oii;
    }
    #undef OF
}

// -------- sghat = attn x svhat
__global__ void k_ghat(const float* __restrict__ attn, const float* __restrict__ vin,
                       float* __restrict__ gout, int ncols) {
    int b = blockIdx.x, h = blockIdx.y, c0 = blockIdx.z * 256;
    __shared__ float a_sh[1024];
    __shared__ float vs[32 * 256];
    for (int t = threadIdx.x; t < 1024; t += 256)
        a_sh[t] = attn[(size_t)(b * 32 + h) * 1024 + t];
    for (int t = threadIdx.x; t < 8192; t += 256) {
        int s = t >> 8, c = t & 255;
        vs[t] = vin[(size_t)((b * 32 + s) * 32 + h) * ncols + c0 + c];
    }
    __syncthreads();
    int tq = threadIdx.x >> 5;
    int cg = threadIdx.x & 31;
    float acc[4][8];
    #pragma unroll
    for (int r = 0; r < 4; r++)
        #pragma unroll
        for (int cc = 0; cc < 8; cc++) acc[r][cc] = 0.f;
    for (int s = 0; s < 32; s++) {
        float a0 = a_sh[(tq * 4 + 0) * 32 + s];
        float a1 = a_sh[(tq * 4 + 1) * 32 + s];
        float a2 = a_sh[(tq * 4 + 2) * 32 + s];
        float a3 = a_sh[(tq * 4 + 3) * 32 + s];
        const float* vp = vs + s * 256 + cg * 8;
        #pragma unroll
        for (int cc = 0; cc < 8; cc++) {
            float v = vp[cc];
            acc[0][cc] += a0 * v; acc[1][cc] += a1 * v;
            acc[2][cc] += a2 * v; acc[3][cc] += a3 * v;
        }
    }
    #pragma unroll
    for (int r = 0; r < 4; r++)
        #pragma unroll
        for (int cc = 0; cc < 8; cc++)
            gout[(size_t)((b * 32 + tq * 4 + r) * 32 + h) * ncols + c0 + cg * 8 + cc] = acc[r][cc];
}

// -------- fused (attn x vhat) x wP -> PF partials; grid (b=2, mc=16, hg=8)
__global__ void k_gpf(const float* __restrict__ attn, const float* __restrict__ vhat,
                      const float* __restrict__ wP, float* __restrict__ PFp) {
    int b = blockIdx.x, mc = blockIdx.y, hg = blockIdx.z;
    __shared__ float a_sh[1024];
    __shared__ float vs[8192];
    int tid = threadIdx.x;
    int tq = tid >> 5, mg = tid & 31;
    float accr[4][4], acci[4][4];
    #pragma unroll
    for (int r = 0; r < 4; r++)
        #pragma unroll
        for (int m = 0; m < 4; m++) { accr[r][m] = 0.f; acci[r][m] = 0.f; }
    for (int hh = 0; hh < 4; hh++) {
        int h = hg * 4 + hh;
        __syncthreads();
        for (int t = tid; t < 1024; t += 256)
            a_sh[t] = attn[(size_t)(b * 32 + h) * 1024 + t];
        for (int t = tid; t < 8192; t += 256) {
            int s = t >> 8, c = t & 255;
            vs[t] = vhat[((size_t)((b * 32 + s) * 32 + h) * 2048 + mc * 128) * 2 + c];
        }
        __syncthreads();
        float tr[4][4], ti_[4][4];
        #pragma unroll
        for (int r = 0; r < 4; r++)
            #pragma unroll
            for (int m = 0; m < 4; m++) { tr[r][m] = 0.f; ti_[r][m] = 0.f; }
        #pragma unroll 4
        for (int s = 0; s < 32; s++) {
            float a0 = a_sh[(tq * 4 + 0) * 32 + s];
            float a1 = a_sh[(tq * 4 + 1) * 32 + s];
            float a2 = a_sh[(tq * 4 + 2) * 32 + s];
            float a3 = a_sh[(tq * 4 + 3) * 32 + s];
            const float* vp = vs + s * 256 + mg * 8;
            #pragma unroll
            for (int m = 0; m < 4; m++) {
                float vre = vp[m * 2], vim = vp[m * 2 + 1];
                tr[0][m] += a0 * vre; ti_[0][m] += a0 * vim;
                tr[1][m] += a1 * vre; ti_[1][m] += a1 * vim;
                tr[2][m] += a2 * vre; ti_[2][m] += a2 * vim;
                tr[3][m] += a3 * vre; ti_[3][m] += a3 * vim;
            }
        }
        #pragma unroll
        for (int m = 0; m < 4; m++) {
            int M = mc * 128 + mg * 4 + m;
            int jj = M >> 5, c = M & 31;
            int sgn = jj < 32 ? 0 : 1, jjm = jj & 31;
            const float* wp = wP + (((size_t)(sgn * 32 + h) * 32 + jjm) * 32 + c) * 2;
            float wr = wp[0], wi = wp[1];
            #pragma unroll
            for (int r = 0; r < 4; r++) {
                accr[r][m] += tr[r][m] * wr - ti_[r][m] * wi;
                acci[r][m] += tr[r][m] * wi + ti_[r][m] * wr;
            }
        }
    }
    #pragma unroll
    for (int r = 0; r < 4; r++) {
        int i = b * 32 + tq * 4 + r;
        #pragma unroll
        for (int m = 0; m < 4; m++) {
            int M = mc * 128 + mg * 4 + m;
            size_t o = (size_t)hg * (NI * 4096) + (size_t)i * 4096 + (size_t)M * 2;
            PFp[o] = accr[r][m]; PFp[o + 1] = acci[r][m];
        }
    }
}

// -------- window extras into PF partial slot 0
__global__ void k_pfw(const float* __restrict__ sghat, const float* __restrict__ wPs,
                      float* __restrict__ PFp) {
    int i = blockIdx.x;
    int w = blockIdx.y * 256 + threadIdx.x;
    __shared__ float wps_[32];
    if (threadIdx.x < 32) wps_[threadIdx.x] = wPs[threadIdx.x];
    __syncthreads();
    int jm = w >> 4, c = w & 15;
    int jj = jm < 16 ? jm : jm + 32;
    int t = jj * 32 + c;
    float re = 0.f, im = 0.f;
    #pragma unroll 4
    for (int h = 0; h < 32; h++) {
        const float* sg = sghat + ((size_t)(i * 32 + h) * 512 + w) * 2;
        re += wps_[h] * sg[0]; im += wps_[h] * sg[1];
    }
    size_t o = (size_t)i * 4096 + (size_t)t * 2;
    PFp[o] += re; PFp[o + 1] += im;
}

// -------- token mix y2
__global__ void k_tokmix(const float* __restrict__ attn, const float* __restrict__ xan,
                         const float* __restrict__ wPs, const float* __restrict__ wVs,
                         const float* __restrict__ bVs, const float* __restrict__ bPs,
                         float* __restrict__ y2) {
    int b = blockIdx.x;
    int pbase = blockIdx.y * 256;
    int tid = threadIdx.x;
    __shared__ float C[1024];
    __shared__ float xs[32 * 256];
    __shared__ float cb_s;
    {
        int t = tid >> 3, s0 = (tid & 7) * 4;
        float c0 = 0.f, c1 = 0.f, c2 = 0.f, c3 = 0.f;
        for (int h = 0; h < 32; h++) {
            float w = wPs[h] * wVs[h];
            const float* ap = attn + (size_t)(b * 32 + h) * 1024 + t * 32 + s0;
            c0 += w * ap[0]; c1 += w * ap[1]; c2 += w * ap[2]; c3 += w * ap[3];
        }
        C[t * 32 + s0] = c0; C[t * 32 + s0 + 1] = c1;
        C[t * 32 + s0 + 2] = c2; C[t * 32 + s0 + 3] = c3;
    }
    if (tid == 0) {
        float cb = bPs[0];
        for (int h = 0; h < 32; h++) cb += wPs[h] * bVs[h];
        cb_s = cb;
    }
    for (int t = tid; t < 8192; t += 256) {
        int s = t >> 8, c = t & 255;
        xs[t] = xan[(size_t)(b * 32 + s) * HW + pbase + c];
    }
    __syncthreads();
    int t = tid >> 3, pg = tid & 7;
    float acc[32];
    #pragma unroll
    for (int pp = 0; pp < 32; pp++) acc[pp] = 0.f;
    for (int s = 0; s < 32; s++) {
        float cc = C[t * 32 + s];
        const float* xp = xs + s * 256 + pg * 32;
        #pragma unroll
        for (int pp = 0; pp < 32; pp++) acc[pp] += cc * xp[pp];
    }
    float cb = cb_s;
    #pragma unroll
    for (int pp = 0; pp < 32; pp++)
        y2[(size_t)(b * 32 + t) * HW + pbase + pg * 32 + pp] = acc[pp] + cb;
}

extern "C" void kernel_launch(void* const* d_in, const int* in_sizes, int n_in,
                              void* d_out, int out_size) {
    const float* x    = (const float*)d_in[0];
    const float* wK   = (const float*)d_in[1];
    const float* wKs  = (const float*)d_in[2];
    const float* bKs  = (const float*)d_in[3];
    const float* wQ   = (const float*)d_in[4];
    const float* wQs  = (const float*)d_in[5];
    const float* bQs  = (const float*)d_in[6];
    const float* wV   = (const float*)d_in[7];
    const float* wVs  = (const float*)d_in[8];
    const float* bVs  = (const float*)d_in[9];
    const float* wP   = (const float*)d_in[10];
    const float* wPs  = (const float*)d_in[11];
    const float* bPs  = (const float*)d_in[12];
    const float* wM0  = (const float*)d_in[13];
    const float* wM0s = (const float*)d_in[14];
    const float* bM0s = (const float*)d_in[15];
    const float* wM1  = (const float*)d_in[16];
    const float* wM1s = (const float*)d_in[17];
    const float* bM1s = (const float*)d_in[18];
    const float* ng   = (const float*)d_in[19];
    const float* nb   = (const float*)d_in[20];
    float* out = (float*)d_out;

    float *p_xan, *p_F1, *p_F2, *p_u, *p_v, *p_rcq, *p_rck, *p_scpA, *p_scp0, *p_attn;
    float *p_vhat, *p_svhat, *p_sghat, *p_PFp, *p_y2;
    float *p_fno, *p_att, *p_an, *p_m, *p_MF1, *p_MF2;
    cudaGetSymbolAddress((void**)&p_xan,   s_xan);
    cudaGetSymbolAddress((void**)&p_F1,    s_F1);
    cudaGetSymbolAddress((void**)&p_F2,    s_F2);
    cudaGetSymbolAddress((void**)&p_u,     s_u);
    cudaGetSymbolAddress((void**)&p_v,     s_v);
    cudaGetSymbolAddress((void**)&p_rcq,   s_rcq);
    cudaGetSymbolAddress((void**)&p_rck,   s_rck);
    cudaGetSymbolAddress((void**)&p_scpA,  s_scpA);
    cudaGetSymbolAddress((void**)&p_scp0,  s_scp0);
    cudaGetSymbolAddress((void**)&p_attn,  s_attn);
    cudaGetSymbolAddress((void**)&p_vhat,  s_vhat);
    cudaGetSymbolAddress((void**)&p_svhat, s_svhat);
    cudaGetSymbolAddress((void**)&p_sghat, s_sghat);
    cudaGetSymbolAddress((void**)&p_PFp,   s_PFp);
    cudaGetSymbolAddress((void**)&p_y2,    s_y2);
    cudaGetSymbolAddress((void**)&p_fno,   s_fno);
    cudaGetSymbolAddress((void**)&p_att,   s_att);
    cudaGetSymbolAddress((void**)&p_an,    s_an);
    cudaGetSymbolAddress((void**)&p_m,     s_m);
    cudaGetSymbolAddress((void**)&p_MF1,   s_MF1);
    cudaGetSymbolAddress((void**)&p_MF2,   s_MF2);

    const size_t PSTRIDE = (size_t)NI * 4096;

    k_init<<<1, 128>>>();

    // xa_n (idx0) + partial spectrum
    k_inorm<<<NI, 512>>>(x, nullptr, p_xan, ng, nb, 0, nullptr);
    k_fwd1<33><<<dim3(NI, 4), 264>>>(p_xan, p_F1);
    k_fwd2<<<dim3(NI, 4), 576>>>(p_F1, p_F2, 33);

    // mode-space attention scores (Parseval, split support/complement)
    k_rhat<<<NI, 256>>>(p_F2, p_rcq, p_rck);
    k_uv<<<dim3(NI, 4), 256>>>(p_F2, wQ, wQs, bQs, wK, wKs, bKs, p_u, p_v);
    k_gemm_part<<<dim3(2, 5), 256>>>(p_rcq, p_rck, p_scp0, 3200, 1);
    k_gemm_part<<<dim3(64, 3), 256>>>(p_u, p_v, p_scpA, 1152, 32);
    k_softmax<<<64, 1024>>>(p_scpA, p_scp0, wQs, wKs, p_attn);

    // mode-space V / attention / projection
    k_vhat<<<dim3(NI, NH), 256>>>(p_F2, wV, wVs, bVs, p_vhat, p_svhat);
    k_ghat<<<dim3(2, 32, 4), 256>>>(p_attn, p_svhat, p_sghat, 1024);
    k_gpf<<<dim3(2, 16, 8), 256>>>(p_attn, p_vhat, wP, p_PFp);
    k_pfw<<<dim3(NI, 2), 256>>>(p_sghat, wPs, p_PFp);
    k_tokmix<<<dim3(2, 64), 256>>>(p_attn, p_xan, wPs, wVs, bVs, bPs, p_y2);
    k_inv2<<<dim3(NI, 4), 512>>>(p_PFp, nullptr, p_fno, 32, 128, p_y2, 8, PSTRIDE);

    // att = IN1(projd + xa); an = IN2(att)
    k_norm12<<<NI, 512>>>(p_fno, x, p_att, p_an, ng, nb);

    // mixer layer 0 (idx3 + gelu)
    k_fwd1<32><<<dim3(NI, 4), 256>>>(p_an, p_MF1);
    k_fwd2<<<dim3(NI, 4), 512>>>(p_MF1, p_MF2, 32);
    k_inv2<<<dim3(NI, 4), 512>>>(p_MF2, wM0, p_fno, 32, 128, nullptr, 1, 0);
    k_normeps<<<NI, 512>>>(p_fno, p_an, p_m, ng, nb, 3, wM0s, bM0s, 1);

    // mixer layer 1 (idx4)
    k_fwd1<32><<<dim3(NI, 4), 256>>>(p_m, p_MF1);
    k_fwd2<<<dim3(NI, 4), 512>>>(p_MF1, p_MF2, 32);
    k_inv2<<<dim3(NI, 4), 512>>>(p_MF2, wM1, p_fno, 32, 128, nullptr, 1, 0);
    k_normeps<<<NI, 512>>>(p_fno, p_m, p_m, ng, nb, 4, wM1s, bM1s, 0);

    // output = IN5(m) + att
    k_inorm<<<NI, 512>>>(p_m, nullptr, out, ng, nb, 5, p_att);
}